// round 12
// baseline (speedup 1.0000x reference)
#include <cuda_runtime.h>
#include <cuda_bf16.h>
#include <cuda_fp16.h>
#include <cstdint>
#include <math.h>

#define NB 2
#define NS 2048
#define ND 1024
#define NH 16
#define NDH 64
#define MT (NB*NS)          // 4096 rows in all GEMMs
#define LOG2E 1.4426950408889634f

// Scratch (allocation-free rule: __device__ globals)
__device__ float g_q [NB*NH*NS*NDH];   // [B,H,S,DH] fp32 (row-major)
// GEMM operands, fp16 fragment layouts (tile = 4096 halves = 8KB per array):
//   A-layout [mb][kb][tile], B-layout [nb][kb][tile]
__device__ unsigned short g_xh [MT*ND];   // X hi
__device__ unsigned short g_xl [MT*ND];   // X lo
__device__ unsigned short g_wq16[ND*ND];  // 32*W in fp16, B-frag layout
__device__ unsigned short g_wk16[ND*ND];
__device__ unsigned short g_wv16[ND*ND];
__device__ unsigned short g_wo16[ND*ND];
__device__ unsigned short g_aoh[MT*ND];   // attention out hi (A-frag layout)
__device__ unsigned short g_aol[MT*ND];   // attention out lo
// K: fp16 (natural [bh][s][d]); V: fp16 (transposed [bh][d][s])
__device__ unsigned short g_kf16 [NB*NH*NS*NDH];
__device__ unsigned short g_vt16 [NB*NH*NS*NDH];

// ===========================================================================
// Helpers
// ===========================================================================
__device__ __forceinline__ uint32_t smem_u32(const void* p) {
    uint32_t a;
    asm("{ .reg .u64 t; cvta.to.shared.u64 t, %1; cvt.u32.u64 %0, t; }"
        : "=r"(a) : "l"(p));
    return a;
}

__device__ __forceinline__ float ex2f(float x) {      // bare MUFU.EX2, ftz
    float y;
    asm("ex2.approx.ftz.f32 %0, %1;" : "=f"(y) : "f"(x));
    return y;
}

__device__ __forceinline__ void mma_fp16(float (&c)[4],
                                         const uint32_t (&a)[4],
                                         const uint32_t (&b)[2]) {
    asm volatile(
        "mma.sync.aligned.m16n8k16.row.col.f32.f16.f16.f32 "
        "{%0,%1,%2,%3}, {%4,%5,%6,%7}, {%8,%9}, {%0,%1,%2,%3};"
        : "+f"(c[0]), "+f"(c[1]), "+f"(c[2]), "+f"(c[3])
        : "r"(a[0]), "r"(a[1]), "r"(a[2]), "r"(a[3]), "r"(b[0]), "r"(b[1]));
}

__device__ __forceinline__ uint32_t pack_h2(float x0, float x1) {
    __half2 h = __floats2half2_rn(x0, x1);
    return *(uint32_t*)&h;
}

// Split a pair of floats into packed fp16x2 hi + lo
__device__ __forceinline__ void split2h(float x0, float x1,
                                        uint32_t& hi, uint32_t& lo) {
    __half2 h = __floats2half2_rn(x0, x1);
    float2 hf = __half22float2(h);
    __half2 l = __floats2half2_rn(x0 - hf.x, x1 - hf.y);
    hi = *(uint32_t*)&h;
    lo = *(uint32_t*)&l;
}

#define CP16(dst, src) \
    asm volatile("cp.async.cg.shared.global [%0], [%1], 16;" \
                 :: "r"(dst), "l"(src))
#define CP_COMMIT() asm volatile("cp.async.commit_group;" ::: "memory")
#define CP_WAIT1()  asm volatile("cp.async.wait_group 1;" ::: "memory")
#define CP_WAIT0()  asm volatile("cp.async.wait_group 0;" ::: "memory")

// A-fragment fp16 uint32 index for element pair (m, k even):
//   tile 2048 u32; u32 = ((c*8+mf)*32 + g*4+tg)*4 + khalf8*2 + mhalf
__device__ __forceinline__ size_t af16_off(int m, int k) {
    const int mb = m >> 7, kb = k >> 5, c = (k >> 4) & 1;
    const int mf = (m >> 4) & 7, g = m & 7, mhalf = (m >> 3) & 1;
    const int tg = (k >> 1) & 3, khalf8 = (k >> 3) & 1;
    return ((size_t)(mb * 32 + kb)) * 2048
         + (size_t)((((c * 8 + mf) * 32 + g * 4 + tg) * 4) + khalf8 * 2 + mhalf);
}

#define AF_TILE_B 8192
#define STAGE_B   24576            // A_hi 8K + A_lo 8K + B 8K
#define GEMM_SMEM (3 * STAGE_B)    // 73728, 3-stage

// ---------------------------------------------------------------------------
// fp16 2-term GEMM core: C = (A_hi + A_lo) * B, fp32 accum.
// A-frag = 1 LDS.128 per term, B-frag = 1 LDS.64; linear 8KB tile copies.
// 3-stage, one barrier per k-tile. Caller scales epilogue by 1/32 (B = 32*W).
// ---------------------------------------------------------------------------
__device__ __forceinline__ void gemm_f16_core(
    const unsigned short* __restrict__ Ah,
    const unsigned short* __restrict__ Al,
    const unsigned short* __restrict__ Bf,
    char* sm, int mblk, int nblk, float (&acc)[4][4][4])
{
    const int tid  = threadIdx.x;
    const int wid  = tid >> 5, lane = tid & 31;
    const int wm   = wid >> 2, wn = wid & 3;

    #pragma unroll
    for (int mt = 0; mt < 4; mt++)
        #pragma unroll
        for (int nt = 0; nt < 4; nt++)
            #pragma unroll
            for (int i = 0; i < 4; i++) acc[mt][nt][i] = 0.f;

    const uint32_t sm_u = smem_u32(sm);

    auto issue_tile = [&](int kt, int bf) {
        const unsigned short* sAh = Ah + ((size_t)(mblk * 32 + kt)) * 4096;
        const unsigned short* sAl = Al + ((size_t)(mblk * 32 + kt)) * 4096;
        const unsigned short* sB  = Bf + ((size_t)(nblk * 32 + kt)) * 4096;
        const uint32_t st = sm_u + bf * STAGE_B;
        #pragma unroll
        for (int i = 0; i < 2; i++) {
            const int f = tid + i * 256;
            CP16(st +             f * 16, sAh + f * 8);
            CP16(st +  8192 +     f * 16, sAl + f * 8);
            CP16(st + 16384 +     f * 16, sB  + f * 8);
        }
        CP_COMMIT();
    };

    issue_tile(0, 0);
    issue_tile(1, 1);

    for (int kt = 0; kt < 32; kt++) {
        const int bf = kt % 3;
        if (kt == 31) CP_WAIT0(); else CP_WAIT1();
        __syncthreads();
        if (kt + 2 < 32) issue_tile(kt + 2, (kt + 2) % 3);

        const uint4* Ah4 = (const uint4*)(sm + bf * STAGE_B);
        const uint4* Al4 = (const uint4*)(sm + bf * STAGE_B + 8192);
        const uint2* B2  = (const uint2*)(sm + bf * STAGE_B + 16384);

        #pragma unroll
        for (int c = 0; c < 2; c++) {
            uint2 bv[4];
            #pragma unroll
            for (int nt = 0; nt < 4; nt++)
                bv[nt] = B2[(c * 16 + wn * 4 + nt) * 32 + lane];

            uint32_t a[4][4];
            #pragma unroll
            for (int mt = 0; mt < 4; mt++) {
                uint4 t = Ah4[(c * 8 + wm * 4 + mt) * 32 + lane];
                a[mt][0] = t.x; a[mt][1] = t.y; a[mt][2] = t.z; a[mt][3] = t.w;
            }
            #pragma unroll
            for (int mt = 0; mt < 4; mt++)
                #pragma unroll
                for (int nt = 0; nt < 4; nt++) {
                    uint32_t b2[2] = { bv[nt].x, bv[nt].y };
                    mma_fp16(acc[mt][nt], a[mt], b2);
                }
            #pragma unroll
            for (int mt = 0; mt < 4; mt++) {
                uint4 t = Al4[(c * 8 + wm * 4 + mt) * 32 + lane];
                a[mt][0] = t.x; a[mt][1] = t.y; a[mt][2] = t.z; a[mt][3] = t.w;
            }
            #pragma unroll
            for (int mt = 0; mt < 4; mt++)
                #pragma unroll
                for (int nt = 0; nt < 4; nt++) {
                    uint32_t b2[2] = { bv[nt].x, bv[nt].y };
                    mma_fp16(acc[mt][nt], a[mt], b2);
                }
        }
    }
    __syncthreads();   // protect smem reuse by epilogue
}

// ---------------------------------------------------------------------------
// Round prep: X -> fp16 hi/lo (A-frag); W -> fp16 of 32*W (B-frag).
// ---------------------------------------------------------------------------
__global__ __launch_bounds__(256) void round_prep(
    const float* __restrict__ X,  const float* __restrict__ Wq,
    const float* __restrict__ Wk, const float* __restrict__ Wv,
    const float* __restrict__ Wo)
{
    const int z = blockIdx.y;
    if (z == 0) {
        for (int t = blockIdx.x * 256 + threadIdx.x; t < MT * ND / 2;
             t += gridDim.x * 256) {
            const int tile = t >> 11, w = t & 2047;
            const int j = w & 3, lane = (w >> 2) & 31;
            const int mf = (w >> 7) & 7, c = (w >> 10) & 1;
            const int mb = tile >> 5, kb = tile & 31;
            const int g = lane >> 2, tg = lane & 3;
            const int m = mb * 128 + mf * 16 + (j & 1) * 8 + g;
            const int k = kb * 32 + c * 16 + (j >> 1) * 8 + 2 * tg;
            uint32_t hi, lo;
            split2h(X[(size_t)m * ND + k], X[(size_t)m * ND + k + 1], hi, lo);
            ((uint32_t*)g_xh)[t] = hi;
            ((uint32_t*)g_xl)[t] = lo;
        }
    } else {
        const float* s = (z == 1) ? Wq : (z == 2) ? Wk : (z == 3) ? Wv : Wo;
        unsigned short* d = (z == 1) ? g_wq16 : (z == 2) ? g_wk16
                          : (z == 3) ? g_wv16 : g_wo16;
        for (int t = blockIdx.x * 256 + threadIdx.x; t < ND * ND / 2;
             t += gridDim.x * 256) {
            const int tile = t >> 11, w = t & 2047;
            const int jj = w & 1, lane = (w >> 1) & 31;
            const int nf = (w >> 6) & 15, c = (w >> 10) & 1;
            const int nb = tile >> 5, kb = tile & 31;
            const int g = lane >> 2, tg = lane & 3;
            const int k = kb * 32 + c * 16 + jj * 8 + 2 * tg;
            const int n = nb * 128 + nf * 8 + g;
            ((uint32_t*)d)[t] = pack_h2(32.f * s[(size_t)k * ND + n],
                                        32.f * s[(size_t)(k + 1) * ND + n]);
        }
    }
}

// ---------------------------------------------------------------------------
// QKV projection: z=0 -> Q fp32 [B,H,S,DH] (+bias+emotion);
//                 z=1 -> K fp16 [bh][s][d];
//                 z=2 -> V fp16 transposed [bh][d][s] (via smem transpose).
// Accumulator is 32x the true value (B = 32*W): scale by 1/32 in epilogue.
// ---------------------------------------------------------------------------
__global__ __launch_bounds__(256, 2) void qkv_gemm(
    const float* __restrict__ bq, const float* __restrict__ bk,
    const float* __restrict__ bv, const float* __restrict__ emo)
{
    extern __shared__ char sm[];
    const int z = blockIdx.z;
    const unsigned short* W = (z == 0) ? g_wq16 : (z == 1) ? g_wk16 : g_wv16;
    const float* bias = (z == 0) ? bq : (z == 1) ? bk : bv;

    const int m0 = blockIdx.y * 128, n0 = blockIdx.x * 128;
    float acc[4][4][4];
    gemm_f16_core(g_xh, g_xl, W, sm, blockIdx.y, blockIdx.x, acc);

    const int tid = threadIdx.x, wid = tid >> 5, lane = tid & 31;
    const int wm = wid >> 2, wn = wid & 3;
    const int g = lane >> 2, tg = lane & 3;
    const float sc = 0.03125f;

    if (z == 0) {
        #pragma unroll
        for (int mt = 0; mt < 4; mt++) {
            #pragma unroll
            for (int nt = 0; nt < 4; nt++) {
                const int n = n0 + wn * 32 + nt * 8 + 2 * tg;
                const int h = n >> 6, dh = n & 63;
                float b0 = bias[n]     + emo[n];
                float b1 = bias[n + 1] + emo[n + 1];
                #pragma unroll
                for (int half = 0; half < 2; half++) {
                    const int r = m0 + wm * 64 + mt * 16 + g + half * 8;
                    const int bb = r >> 11, s = r & (NS - 1);
                    float2 v = make_float2(acc[mt][nt][2 * half] * sc + b0,
                                           acc[mt][nt][2 * half + 1] * sc + b1);
                    *(float2*)&g_q[(((size_t)bb * NH + h) * NS + s) * NDH + dh] = v;
                }
            }
        }
    } else if (z == 1) {
        #pragma unroll
        for (int mt = 0; mt < 4; mt++) {
            #pragma unroll
            for (int nt = 0; nt < 4; nt++) {
                const int n = n0 + wn * 32 + nt * 8 + 2 * tg;
                const int h = n >> 6, dh = n & 63;
                float b0 = bias[n], b1 = bias[n + 1];
                #pragma unroll
                for (int half = 0; half < 2; half++) {
                    const int r = m0 + wm * 64 + mt * 16 + g + half * 8;
                    const int bb = r >> 11, s = r & (NS - 1);
                    uint32_t v = pack_h2(acc[mt][nt][2 * half] * sc + b0,
                                         acc[mt][nt][2 * half + 1] * sc + b1);
                    *(uint32_t*)&g_kf16[(((size_t)bb * NH + h) * NS + s) * NDH + dh] = v;
                }
            }
        }
    } else {
        // V fp16 transposed via smem
        unsigned short* vt = (unsigned short*)sm;   // stride 136 ushorts
        #pragma unroll
        for (int mt = 0; mt < 4; mt++) {
            #pragma unroll
            for (int nt = 0; nt < 4; nt++) {
                const int nl = wn * 32 + nt * 8 + 2 * tg;
                float b0 = bias[n0 + nl], b1 = bias[n0 + nl + 1];
                #pragma unroll
                for (int half = 0; half < 2; half++) {
                    const int sl = wm * 64 + mt * 16 + g + half * 8;
                    vt[nl * 136 + sl]       = __half_as_ushort(
                        __float2half_rn(acc[mt][nt][2 * half] * sc + b0));
                    vt[(nl + 1) * 136 + sl] = __half_as_ushort(
                        __float2half_rn(acc[mt][nt][2 * half + 1] * sc + b1));
                }
            }
        }
        __syncthreads();
        const int bb = m0 >> 11, sbase = m0 & (NS - 1);
        for (int i = tid; i < 128 * 64; i += 256) {
            const int nl = i >> 6, s2 = (i & 63) * 2;
            const int n = n0 + nl, h = n >> 6, dh = n & 63;
            *(uint32_t*)&g_vt16[(((size_t)bb * NH + h) * NDH + dh) * NS + sbase + s2] =
                *(const uint32_t*)&vt[nl * 136 + s2];
        }
    }
}

// ---------------------------------------------------------------------------
// Output projection: (g_aoh+g_aol) @ g_wo16 (=32*Wo) -> out = acc/32 + bo
// ---------------------------------------------------------------------------
__global__ __launch_bounds__(256, 2) void out_gemm(
    const float* __restrict__ bo, float* __restrict__ out)
{
    extern __shared__ char sm[];
    const int m0 = blockIdx.y * 128, n0 = blockIdx.x * 128;
    float acc[4][4][4];
    gemm_f16_core(g_aoh, g_aol, g_wo16, sm, blockIdx.y, blockIdx.x, acc);

    const int tid = threadIdx.x, wid = tid >> 5, lane = tid & 31;
    const int wm = wid >> 2, wn = wid & 3;
    const int g = lane >> 2, tg = lane & 3;
    const float sc = 0.03125f;

    #pragma unroll
    for (int mt = 0; mt < 4; mt++) {
        #pragma unroll
        for (int nt = 0; nt < 4; nt++) {
            const int n = n0 + wn * 32 + nt * 8 + 2 * tg;
            float b0 = bo[n], b1 = bo[n + 1];
            #pragma unroll
            for (int half = 0; half < 2; half++) {
                const int r = m0 + wm * 64 + mt * 16 + g + half * 8;
                float2 v = make_float2(acc[mt][nt][2 * half] * sc + b0,
                                       acc[mt][nt][2 * half + 1] * sc + b1);
                *(float2*)&out[(size_t)r * ND + n] = v;
            }
        }
    }
}

// ---------------------------------------------------------------------------
// Flash attention (mainloop unchanged): S = QK^T fp16, O = PV fp16, log2
// softmax; epilogue writes g_aoh/g_aol (fp16 hi/lo, A-fragment layout).
// ---------------------------------------------------------------------------
#define KV_STRIDE 72
#define ARR_B     (64 * 144)
#define ATT_STAGE (2 * ARR_B)
#define ATT_SMEM  (3 * ATT_STAGE)

__global__ __launch_bounds__(256, 2) void attn_kernel(const int* __restrict__ mask)
{
    extern __shared__ char att_sm[];
    __shared__ float mb[3][64];

    const int bh = blockIdx.y;
    const int b  = bh >> 4;
    const int h  = bh & 15;
    const int q0 = blockIdx.x * 128;
    const float* Qp = g_q + (size_t)bh * NS * NDH;
    const unsigned short* KF = g_kf16 + (size_t)bh * NS * NDH;   // [s][d] fp16
    const unsigned short* VT = g_vt16 + (size_t)bh * NS * NDH;   // [d][s] fp16
    const int* mrow = mask + b * NS;

    const int tid = threadIdx.x, wid = tid >> 5, lane = tid & 31;
    const int g = lane >> 2, tg = lane & 3;
    const uint32_t sb = smem_u32(att_sm);

    auto issue = [&](int kb, int bf) {
        const int k0g = kb * 64;
        const uint32_t st = sb + bf * ATT_STAGE;
        #pragma unroll
        for (int i = 0; i < 2; i++) {
            int f = tid + i * 256;
            int row = f >> 3, q = f & 7;
            CP16(st + 0 * ARR_B + row * 144 + q * 16,
                 KF + (size_t)(k0g + row) * NDH + q * 8);
            CP16(st + 1 * ARR_B + row * 144 + q * 16,
                 VT + (size_t)row * NS + k0g + q * 8);
        }
        CP_COMMIT();
    };

    const float qs = 0.125f * LOG2E;
    uint32_t qh[4][4];
    {
        const float* q0p = Qp + (size_t)(q0 + wid * 16 + g) * NDH;
        const float* q1p = q0p + 8 * NDH;
        #pragma unroll
        for (int kk = 0; kk < 4; kk++) {
            float2 x;
            x = *(const float2*)(q0p + kk * 16 + 2 * tg);
            qh[kk][0] = pack_h2(qs * x.x, qs * x.y);
            x = *(const float2*)(q1p + kk * 16 + 2 * tg);
            qh[kk][1] = pack_h2(qs * x.x, qs * x.y);
            x = *(const float2*)(q0p + kk * 16 + 2 * tg + 8);
            qh[kk][2] = pack_h2(qs * x.x, qs * x.y);
            x = *(const float2*)(q1p + kk * 16 + 2 * tg + 8);
            qh[kk][3] = pack_h2(qs * x.x, qs * x.y);
        }
    }

    float o[8][4];
    #pragma unroll
    for (int nt = 0; nt < 8; nt++)
        #pragma unroll
        for (int i = 0; i < 4; i++) o[nt][i] = 0.f;
    float mrun[2] = {-1e30f, -1e30f}, lrun[2] = {0.f, 0.f};

    issue(0, 0);
    issue(1, 1);
    if (tid < 64) {
        mb[0][tid] = mrow[tid]      ? 0.f : -1e30f;
        mb[1][tid] = mrow[64 + tid] ? 0.f : -1e30f;
    }

    for (int kb = 0; kb < NS / 64; kb++) {
        const int bf = kb % 3;
        if (kb == NS / 64 - 1) CP_WAIT0(); else CP_WAIT1();
        __syncthreads();
        if (kb + 2 < NS / 64) {
            issue(kb + 2, (kb + 2) % 3);
            if (tid < 64)
                mb[(kb + 2) % 3][tid] = mrow[(kb + 2) * 64 + tid] ? 0.f : -1e30f;
        }

        const unsigned short* Ksm = (const unsigned short*)(att_sm + bf * ATT_STAGE);
        const unsigned short* VTs = Ksm + 64 * KV_STRIDE;

        float sc[8][4];
        #pragma unroll
        for (int nt = 0; nt < 8; nt++)
            #pragma unroll
            for (int i = 0; i < 4; i++) sc[nt][i] = 0.f;

        #pragma unroll
        for (int kk = 0; kk < 4; kk++) {
            #pragma unroll
            for (int nt = 0; nt < 8; nt++) {
                const int base = (nt * 8 + g) * KV_STRIDE + kk * 16 + 2 * tg;
                uint32_t kb2[2] = { *(const uint32_t*)&Ksm[base],
                                    *(const uint32_t*)&Ksm[base + 8] };
                mma_fp16(sc[nt], qh[kk], kb2);
            }
        }

        #pragma unroll
        for (int nt = 0; nt < 8; nt++) {
            float2 mv = *(const float2*)&mb[bf][nt * 8 + 2 * tg];
            sc[nt][0] += mv.x; sc[nt][1] += mv.y;
            sc[nt][2] += mv.x; sc[nt][3] += mv.y;
        }

        #pragma unroll
        for (int r = 0; r < 2; r++) {
            float mx = -1e30f;
            #pragma unroll
            for (int nt = 0; nt < 8; nt++)
                mx = fmaxf(mx, fmaxf(sc[nt][2 * r], sc[nt][2 * r + 1]));
            mx = fmaxf(mx, __shfl_xor_sync(0xffffffffu, mx, 1));
            mx = fmaxf(mx, __shfl_xor_sync(0xffffffffu, mx, 2));
            const float mn = fmaxf(mrun[r], mx);
            float sum = 0.f;
            #pragma unroll
            for (int nt = 0; nt < 8; nt++) {
                float p0 = ex2f(sc[nt][2 * r]     - mn);
                float p1 = ex2f(sc[nt][2 * r + 1] - mn);
                sc[nt][2 * r] = p0; sc[nt][2 * r + 1] = p1;
                sum += p0 + p1;
            }
            sum += __shfl_xor_sync(0xffffffffu, sum, 1);
            sum += __shfl_xor_sync(0xffffffffu, sum, 2);
            const float al = ex2f(mrun[r] - mn);
            lrun[r] = lrun[r] * al + sum;
            mrun[r] = mn;
            #pragma unroll
            for (int nt = 0; nt < 8; nt++) {
                o[nt][2 * r]     *= al;
                o[nt][2 * r + 1] *= al;
            }
        }

        #pragma unroll
        for (int kk = 0; kk < 4; kk++) {
            uint32_t ph[4];
            ph[0] = pack_h2(sc[2 * kk][0],     sc[2 * kk][1]);
            ph[1] = pack_h2(sc[2 * kk][2],     sc[2 * kk][3]);
            ph[2] = pack_h2(sc[2 * kk + 1][0], sc[2 * kk + 1][1]);
            ph[3] = pack_h2(sc[2 * kk + 1][2], sc[2 * kk + 1][3]);
            #pragma unroll
            for (int nt = 0; nt < 8; nt++) {
                const int base = (nt * 8 + g) * KV_STRIDE + kk * 16 + 2 * tg;
                uint32_t v2[2] = { *(const uint32_t*)&VTs[base],
                                   *(const uint32_t*)&VTs[base + 8] };
                mma_fp16(o[nt], ph, v2);
            }
        }
    }

    // ---- normalize + split fp16 hi/lo + write A-frag layout ----
    const float inv0 = 1.0f / lrun[0];
    const float inv1 = 1.0f / lrun[1];
    const int m_lo = b * NS + q0 + wid * 16 + g;
    const int m_hi = m_lo + 8;
    uint32_t* aoh32 = (uint32_t*)g_aoh;
    uint32_t* aol32 = (uint32_t*)g_aol;
    #pragma unroll
    for (int nt = 0; nt < 8; nt++) {
        const int col = h * 64 + nt * 8 + 2 * tg;
        uint32_t hi, lo;
        split2h(o[nt][0] * inv0, o[nt][1] * inv0, hi, lo);
        size_t off = af16_off(m_lo, col);
        aoh32[off] = hi; aol32[off] = lo;
        split2h(o[nt][2] * inv1, o[nt][3] * inv1, hi, lo);
        off = af16_off(m_hi, col);
        aoh32[off] = hi; aol32[off] = lo;
    }
}

// ---------------------------------------------------------------------------
extern "C" void kernel_launch(void* const* d_in, const int* in_sizes, int n_in,
                              void* d_out, int out_size)
{
    const float* hs  = (const float*)d_in[0];
    const int*   msk = (const int*)  d_in[1];
    const float* Wq  = (const float*)d_in[2];
    const float* bq  = (const float*)d_in[3];
    const float* Wk  = (const float*)d_in[4];
    const float* bk  = (const float*)d_in[5];
    const float* Wv  = (const float*)d_in[6];
    const float* bv  = (const float*)d_in[7];
    const float* emo = (const float*)d_in[8];
    const float* Wo  = (const float*)d_in[9];
    const float* bo  = (const float*)d_in[10];
    float* out = (float*)d_out;

    cudaFuncSetAttribute(qkv_gemm, cudaFuncAttributeMaxDynamicSharedMemorySize, GEMM_SMEM);
    cudaFuncSetAttribute(out_gemm, cudaFuncAttributeMaxDynamicSharedMemorySize, GEMM_SMEM);
    cudaFuncSetAttribute(attn_kernel, cudaFuncAttributeMaxDynamicSharedMemorySize, ATT_SMEM);

    dim3 gr(128, 5);
    round_prep<<<gr, 256>>>(hs, Wq, Wk, Wv, Wo);

    dim3 gqkv(ND / 128, MT / 128, 3);
    qkv_gemm<<<gqkv, 256, GEMM_SMEM>>>(bq, bk, bv, emo);

    dim3 gatt(NS / 128, NB * NH);
    attn_kernel<<<gatt, 256, ATT_SMEM>>>(msk);

    dim3 gout(ND / 128, MT / 128);
    out_gemm<<<gout, 256, GEMM_SMEM>>>(bo, out);
}

// round 13
// speedup vs baseline: 1.0518x; 1.0518x over previous
#include <cuda_runtime.h>
#include <cuda_bf16.h>
#include <cuda_fp16.h>
#include <cstdint>
#include <math.h>

#define NB 2
#define NS 2048
#define ND 1024
#define NH 16
#define NDH 64
#define MT (NB*NS)          // 4096 rows in all GEMMs
#define LOG2E 1.4426950408889634f

// Scratch (allocation-free rule: __device__ globals)
__device__ float g_q [NB*NH*NS*NDH];   // [B,H,S,DH] fp32 (row-major)
// GEMM operands, fp16 fragment layouts:
//   A-layout: 64-row tiles [mb64][kb][2048 halves], B-layout [nb][kb][4096 halves]
__device__ unsigned short g_xh [MT*ND];   // X hi
__device__ unsigned short g_xl [MT*ND];   // X lo
__device__ unsigned short g_wq16[ND*ND];  // 32*W in fp16, B-frag layout
__device__ unsigned short g_wk16[ND*ND];
__device__ unsigned short g_wv16[ND*ND];
__device__ unsigned short g_wo16[ND*ND];
__device__ unsigned short g_aoh[MT*ND];   // attention out hi (A-frag layout)
__device__ unsigned short g_aol[MT*ND];   // attention out lo
// K: fp16 (natural [bh][s][d]); V: fp16 (transposed [bh][d][s])
__device__ unsigned short g_kf16 [NB*NH*NS*NDH];
__device__ unsigned short g_vt16 [NB*NH*NS*NDH];

// ===========================================================================
// Helpers
// ===========================================================================
__device__ __forceinline__ uint32_t smem_u32(const void* p) {
    uint32_t a;
    asm("{ .reg .u64 t; cvta.to.shared.u64 t, %1; cvt.u32.u64 %0, t; }"
        : "=r"(a) : "l"(p));
    return a;
}

__device__ __forceinline__ float ex2f(float x) {      // bare MUFU.EX2, ftz
    float y;
    asm("ex2.approx.ftz.f32 %0, %1;" : "=f"(y) : "f"(x));
    return y;
}

__device__ __forceinline__ void mma_fp16(float (&c)[4],
                                         const uint32_t (&a)[4],
                                         const uint32_t (&b)[2]) {
    asm volatile(
        "mma.sync.aligned.m16n8k16.row.col.f32.f16.f16.f32 "
        "{%0,%1,%2,%3}, {%4,%5,%6,%7}, {%8,%9}, {%0,%1,%2,%3};"
        : "+f"(c[0]), "+f"(c[1]), "+f"(c[2]), "+f"(c[3])
        : "r"(a[0]), "r"(a[1]), "r"(a[2]), "r"(a[3]), "r"(b[0]), "r"(b[1]));
}

__device__ __forceinline__ uint32_t pack_h2(float x0, float x1) {
    __half2 h = __floats2half2_rn(x0, x1);
    return *(uint32_t*)&h;
}

// Split a pair of floats into packed fp16x2 hi + lo
__device__ __forceinline__ void split2h(float x0, float x1,
                                        uint32_t& hi, uint32_t& lo) {
    __half2 h = __floats2half2_rn(x0, x1);
    float2 hf = __half22float2(h);
    __half2 l = __floats2half2_rn(x0 - hf.x, x1 - hf.y);
    hi = *(uint32_t*)&h;
    lo = *(uint32_t*)&l;
}

#define CP16(dst, src) \
    asm volatile("cp.async.cg.shared.global [%0], [%1], 16;" \
                 :: "r"(dst), "l"(src))
#define CP_COMMIT() asm volatile("cp.async.commit_group;" ::: "memory")
#define CP_WAIT1()  asm volatile("cp.async.wait_group 1;" ::: "memory")
#define CP_WAIT0()  asm volatile("cp.async.wait_group 0;" ::: "memory")

// A-fragment (64-row tiles) u32 index for element pair (m, k even):
//   tile 1024 u32; u32 = ((c*4+mf)*32 + g*4+tg)*4 + khalf8*2 + mhalf
__device__ __forceinline__ size_t af16_off(int m, int k) {
    const int mb = m >> 6, kb = k >> 5, c = (k >> 4) & 1;
    const int mf = (m >> 4) & 3, g = m & 7, mhalf = (m >> 3) & 1;
    const int tg = (k >> 1) & 3, khalf8 = (k >> 3) & 1;
    return ((size_t)(mb * 32 + kb)) * 1024
         + (size_t)((((c * 4 + mf) * 32 + g * 4 + tg) * 4) + khalf8 * 2 + mhalf);
}

#define STAGE_B   16384            // A_hi 4K + A_lo 4K + B 8K
#define GEMM_SMEM (3 * STAGE_B)    // 49152, 3-stage

// ---------------------------------------------------------------------------
// fp16 2-term GEMM core, 128 threads (4 warps), CTA tile 64m x 128n.
// Warp w owns 64m x 32n (wn = wid). 3-stage, one barrier per k-tile.
// C = (A_hi + A_lo) * B, fp32 accum; caller scales by 1/32 (B = 32*W).
// ---------------------------------------------------------------------------
__device__ __forceinline__ void gemm_f16_core(
    const unsigned short* __restrict__ Ah,
    const unsigned short* __restrict__ Al,
    const unsigned short* __restrict__ Bf,
    char* sm, int mblk, int nblk, float (&acc)[4][4][4])
{
    const int tid  = threadIdx.x;
    const int wn   = tid >> 5, lane = tid & 31;

    #pragma unroll
    for (int mt = 0; mt < 4; mt++)
        #pragma unroll
        for (int nt = 0; nt < 4; nt++)
            #pragma unroll
            for (int i = 0; i < 4; i++) acc[mt][nt][i] = 0.f;

    const uint32_t sm_u = smem_u32(sm);

    auto issue_tile = [&](int kt, int bf) {
        const unsigned short* sAh = Ah + ((size_t)(mblk * 32 + kt)) * 2048;
        const unsigned short* sAl = Al + ((size_t)(mblk * 32 + kt)) * 2048;
        const unsigned short* sB  = Bf + ((size_t)(nblk * 32 + kt)) * 4096;
        const uint32_t st = sm_u + bf * STAGE_B;
        #pragma unroll
        for (int i = 0; i < 2; i++) {
            const int f = tid + i * 128;
            CP16(st +        f * 16, sAh + f * 8);
            CP16(st + 4096 + f * 16, sAl + f * 8);
        }
        #pragma unroll
        for (int i = 0; i < 4; i++) {
            const int f = tid + i * 128;
            CP16(st + 8192 + f * 16, sB + f * 8);
        }
        CP_COMMIT();
    };

    issue_tile(0, 0);
    issue_tile(1, 1);

    for (int kt = 0; kt < 32; kt++) {
        const int bf = kt % 3;
        if (kt == 31) CP_WAIT0(); else CP_WAIT1();
        __syncthreads();
        if (kt + 2 < 32) issue_tile(kt + 2, (kt + 2) % 3);

        const uint4* Ah4 = (const uint4*)(sm + bf * STAGE_B);
        const uint4* Al4 = (const uint4*)(sm + bf * STAGE_B + 4096);
        const uint2* B2  = (const uint2*)(sm + bf * STAGE_B + 8192);

        #pragma unroll
        for (int c = 0; c < 2; c++) {
            uint2 bv[4];
            #pragma unroll
            for (int nt = 0; nt < 4; nt++)
                bv[nt] = B2[(c * 16 + wn * 4 + nt) * 32 + lane];

            uint32_t a[4][4];
            #pragma unroll
            for (int mt = 0; mt < 4; mt++) {
                uint4 t = Ah4[(c * 4 + mt) * 32 + lane];
                a[mt][0] = t.x; a[mt][1] = t.y; a[mt][2] = t.z; a[mt][3] = t.w;
            }
            #pragma unroll
            for (int mt = 0; mt < 4; mt++)
                #pragma unroll
                for (int nt = 0; nt < 4; nt++) {
                    uint32_t b2[2] = { bv[nt].x, bv[nt].y };
                    mma_fp16(acc[mt][nt], a[mt], b2);
                }
            #pragma unroll
            for (int mt = 0; mt < 4; mt++) {
                uint4 t = Al4[(c * 4 + mt) * 32 + lane];
                a[mt][0] = t.x; a[mt][1] = t.y; a[mt][2] = t.z; a[mt][3] = t.w;
            }
            #pragma unroll
            for (int mt = 0; mt < 4; mt++)
                #pragma unroll
                for (int nt = 0; nt < 4; nt++) {
                    uint32_t b2[2] = { bv[nt].x, bv[nt].y };
                    mma_fp16(acc[mt][nt], a[mt], b2);
                }
        }
    }
    __syncthreads();   // protect smem reuse by epilogue
}

// ---------------------------------------------------------------------------
// Round prep: X -> fp16 hi/lo (64-row A-frag tiles); W -> fp16 of 32*W (B-frag).
// ---------------------------------------------------------------------------
__global__ __launch_bounds__(256) void round_prep(
    const float* __restrict__ X,  const float* __restrict__ Wq,
    const float* __restrict__ Wk, const float* __restrict__ Wv,
    const float* __restrict__ Wo)
{
    const int z = blockIdx.y;
    if (z == 0) {
        for (int t = blockIdx.x * 256 + threadIdx.x; t < MT * ND / 2;
             t += gridDim.x * 256) {
            const int tile = t >> 10, w = t & 1023;
            const int j = w & 3, lane = (w >> 2) & 31, grp = w >> 7;
            const int c = grp >> 2, mf = grp & 3;
            const int mb = tile >> 5, kb = tile & 31;
            const int g = lane >> 2, tg = lane & 3;
            const int m = mb * 64 + mf * 16 + (j & 1) * 8 + g;
            const int k = kb * 32 + c * 16 + (j >> 1) * 8 + 2 * tg;
            uint32_t hi, lo;
            split2h(X[(size_t)m * ND + k], X[(size_t)m * ND + k + 1], hi, lo);
            ((uint32_t*)g_xh)[t] = hi;
            ((uint32_t*)g_xl)[t] = lo;
        }
    } else {
        const float* s = (z == 1) ? Wq : (z == 2) ? Wk : (z == 3) ? Wv : Wo;
        unsigned short* d = (z == 1) ? g_wq16 : (z == 2) ? g_wk16
                          : (z == 3) ? g_wv16 : g_wo16;
        for (int t = blockIdx.x * 256 + threadIdx.x; t < ND * ND / 2;
             t += gridDim.x * 256) {
            const int tile = t >> 11, w = t & 2047;
            const int jj = w & 1, lane = (w >> 1) & 31;
            const int nf = (w >> 6) & 15, c = (w >> 10) & 1;
            const int nb = tile >> 5, kb = tile & 31;
            const int g = lane >> 2, tg = lane & 3;
            const int k = kb * 32 + c * 16 + jj * 8 + 2 * tg;
            const int n = nb * 128 + nf * 8 + g;
            ((uint32_t*)d)[t] = pack_h2(32.f * s[(size_t)k * ND + n],
                                        32.f * s[(size_t)(k + 1) * ND + n]);
        }
    }
}

// ---------------------------------------------------------------------------
// QKV projection (128 threads, 64x128 tile): z=0 -> Q fp32 (+bias+emotion);
// z=1 -> K fp16 [bh][s][d]; z=2 -> V fp16 transposed [bh][d][s].
// Epilogue scales acc by 1/32 (B = 32*W).
// ---------------------------------------------------------------------------
__global__ __launch_bounds__(128, 4) void qkv_gemm(
    const float* __restrict__ bq, const float* __restrict__ bk,
    const float* __restrict__ bv, const float* __restrict__ emo)
{
    extern __shared__ char sm[];
    const int z = blockIdx.z;
    const unsigned short* W = (z == 0) ? g_wq16 : (z == 1) ? g_wk16 : g_wv16;
    const float* bias = (z == 0) ? bq : (z == 1) ? bk : bv;

    const int m0 = blockIdx.y * 64, n0 = blockIdx.x * 128;
    float acc[4][4][4];
    gemm_f16_core(g_xh, g_xl, W, sm, blockIdx.y, blockIdx.x, acc);

    const int tid = threadIdx.x, wn = tid >> 5, lane = tid & 31;
    const int g = lane >> 2, tg = lane & 3;
    const float sc = 0.03125f;

    if (z == 0) {
        #pragma unroll
        for (int mt = 0; mt < 4; mt++) {
            #pragma unroll
            for (int nt = 0; nt < 4; nt++) {
                const int n = n0 + wn * 32 + nt * 8 + 2 * tg;
                const int h = n >> 6, dh = n & 63;
                float b0 = bias[n]     + emo[n];
                float b1 = bias[n + 1] + emo[n + 1];
                #pragma unroll
                for (int half = 0; half < 2; half++) {
                    const int r = m0 + mt * 16 + g + half * 8;
                    const int bb = r >> 11, s = r & (NS - 1);
                    float2 v = make_float2(acc[mt][nt][2 * half] * sc + b0,
                                           acc[mt][nt][2 * half + 1] * sc + b1);
                    *(float2*)&g_q[(((size_t)bb * NH + h) * NS + s) * NDH + dh] = v;
                }
            }
        }
    } else if (z == 1) {
        #pragma unroll
        for (int mt = 0; mt < 4; mt++) {
            #pragma unroll
            for (int nt = 0; nt < 4; nt++) {
                const int n = n0 + wn * 32 + nt * 8 + 2 * tg;
                const int h = n >> 6, dh = n & 63;
                float b0 = bias[n], b1 = bias[n + 1];
                #pragma unroll
                for (int half = 0; half < 2; half++) {
                    const int r = m0 + mt * 16 + g + half * 8;
                    const int bb = r >> 11, s = r & (NS - 1);
                    uint32_t v = pack_h2(acc[mt][nt][2 * half] * sc + b0,
                                         acc[mt][nt][2 * half + 1] * sc + b1);
                    *(uint32_t*)&g_kf16[(((size_t)bb * NH + h) * NS + s) * NDH + dh] = v;
                }
            }
        }
    } else {
        // V fp16 transposed via smem: vt[nl][sl], nl 0..127, sl 0..63, stride 72
        unsigned short* vt = (unsigned short*)sm;
        #pragma unroll
        for (int mt = 0; mt < 4; mt++) {
            #pragma unroll
            for (int nt = 0; nt < 4; nt++) {
                const int nl = wn * 32 + nt * 8 + 2 * tg;
                float b0 = bias[n0 + nl], b1 = bias[n0 + nl + 1];
                #pragma unroll
                for (int half = 0; half < 2; half++) {
                    const int sl = mt * 16 + g + half * 8;
                    vt[nl * 72 + sl]       = __half_as_ushort(
                        __float2half_rn(acc[mt][nt][2 * half] * sc + b0));
                    vt[(nl + 1) * 72 + sl] = __half_as_ushort(
                        __float2half_rn(acc[mt][nt][2 * half + 1] * sc + b1));
                }
            }
        }
        __syncthreads();
        const int bb = m0 >> 11, sbase = m0 & (NS - 1);
        for (int i = tid; i < 128 * 32; i += 128) {
            const int nl = i >> 5, s2 = (i & 31) * 2;
            const int n = n0 + nl, h = n >> 6, dh = n & 63;
            *(uint32_t*)&g_vt16[(((size_t)bb * NH + h) * NDH + dh) * NS + sbase + s2] =
                *(const uint32_t*)&vt[nl * 72 + s2];
        }
    }
}

// ---------------------------------------------------------------------------
// Output projection (128 threads): (g_aoh+g_aol) @ g_wo16 -> out = acc/32 + bo
// ---------------------------------------------------------------------------
__global__ __launch_bounds__(128, 4) void out_gemm(
    const float* __restrict__ bo, float* __restrict__ out)
{
    extern __shared__ char sm[];
    const int m0 = blockIdx.y * 64, n0 = blockIdx.x * 128;
    float acc[4][4][4];
    gemm_f16_core(g_aoh, g_aol, g_wo16, sm, blockIdx.y, blockIdx.x, acc);

    const int tid = threadIdx.x, wn = tid >> 5, lane = tid & 31;
    const int g = lane >> 2, tg = lane & 3;
    const float sc = 0.03125f;

    #pragma unroll
    for (int mt = 0; mt < 4; mt++) {
        #pragma unroll
        for (int nt = 0; nt < 4; nt++) {
            const int n = n0 + wn * 32 + nt * 8 + 2 * tg;
            float b0 = bo[n], b1 = bo[n + 1];
            #pragma unroll
            for (int half = 0; half < 2; half++) {
                const int r = m0 + mt * 16 + g + half * 8;
                float2 v = make_float2(acc[mt][nt][2 * half] * sc + b0,
                                       acc[mt][nt][2 * half + 1] * sc + b1);
                *(float2*)&out[(size_t)r * ND + n] = v;
            }
        }
    }
}

// ---------------------------------------------------------------------------
// Flash attention (mainloop unchanged): S = QK^T fp16, O = PV fp16, log2
// softmax; epilogue writes g_aoh/g_aol (fp16 hi/lo, 64-row A-frag layout).
// ---------------------------------------------------------------------------
#define KV_STRIDE 72
#define ARR_B     (64 * 144)
#define ATT_STAGE (2 * ARR_B)
#define ATT_SMEM  (3 * ATT_STAGE)

__global__ __launch_bounds__(256, 2) void attn_kernel(const int* __restrict__ mask)
{
    extern __shared__ char att_sm[];
    __shared__ float mb[3][64];

    const int bh = blockIdx.y;
    const int b  = bh >> 4;
    const int h  = bh & 15;
    const int q0 = blockIdx.x * 128;
    const float* Qp = g_q + (size_t)bh * NS * NDH;
    const unsigned short* KF = g_kf16 + (size_t)bh * NS * NDH;   // [s][d] fp16
    const unsigned short* VT = g_vt16 + (size_t)bh * NS * NDH;   // [d][s] fp16
    const int* mrow = mask + b * NS;

    const int tid = threadIdx.x, wid = tid >> 5, lane = tid & 31;
    const int g = lane >> 2, tg = lane & 3;
    const uint32_t sb = smem_u32(att_sm);

    auto issue = [&](int kb, int bf) {
        const int k0g = kb * 64;
        const uint32_t st = sb + bf * ATT_STAGE;
        #pragma unroll
        for (int i = 0; i < 2; i++) {
            int f = tid + i * 256;
            int row = f >> 3, q = f & 7;
            CP16(st + 0 * ARR_B + row * 144 + q * 16,
                 KF + (size_t)(k0g + row) * NDH + q * 8);
            CP16(st + 1 * ARR_B + row * 144 + q * 16,
                 VT + (size_t)row * NS + k0g + q * 8);
        }
        CP_COMMIT();
    };

    const float qs = 0.125f * LOG2E;
    uint32_t qh[4][4];
    {
        const float* q0p = Qp + (size_t)(q0 + wid * 16 + g) * NDH;
        const float* q1p = q0p + 8 * NDH;
        #pragma unroll
        for (int kk = 0; kk < 4; kk++) {
            float2 x;
            x = *(const float2*)(q0p + kk * 16 + 2 * tg);
            qh[kk][0] = pack_h2(qs * x.x, qs * x.y);
            x = *(const float2*)(q1p + kk * 16 + 2 * tg);
            qh[kk][1] = pack_h2(qs * x.x, qs * x.y);
            x = *(const float2*)(q0p + kk * 16 + 2 * tg + 8);
            qh[kk][2] = pack_h2(qs * x.x, qs * x.y);
            x = *(const float2*)(q1p + kk * 16 + 2 * tg + 8);
            qh[kk][3] = pack_h2(qs * x.x, qs * x.y);
        }
    }

    float o[8][4];
    #pragma unroll
    for (int nt = 0; nt < 8; nt++)
        #pragma unroll
        for (int i = 0; i < 4; i++) o[nt][i] = 0.f;
    float mrun[2] = {-1e30f, -1e30f}, lrun[2] = {0.f, 0.f};

    issue(0, 0);
    issue(1, 1);
    if (tid < 64) {
        mb[0][tid] = mrow[tid]      ? 0.f : -1e30f;
        mb[1][tid] = mrow[64 + tid] ? 0.f : -1e30f;
    }

    for (int kb = 0; kb < NS / 64; kb++) {
        const int bf = kb % 3;
        if (kb == NS / 64 - 1) CP_WAIT0(); else CP_WAIT1();
        __syncthreads();
        if (kb + 2 < NS / 64) {
            issue(kb + 2, (kb + 2) % 3);
            if (tid < 64)
                mb[(kb + 2) % 3][tid] = mrow[(kb + 2) * 64 + tid] ? 0.f : -1e30f;
        }

        const unsigned short* Ksm = (const unsigned short*)(att_sm + bf * ATT_STAGE);
        const unsigned short* VTs = Ksm + 64 * KV_STRIDE;

        float sc[8][4];
        #pragma unroll
        for (int nt = 0; nt < 8; nt++)
            #pragma unroll
            for (int i = 0; i < 4; i++) sc[nt][i] = 0.f;

        #pragma unroll
        for (int kk = 0; kk < 4; kk++) {
            #pragma unroll
            for (int nt = 0; nt < 8; nt++) {
                const int base = (nt * 8 + g) * KV_STRIDE + kk * 16 + 2 * tg;
                uint32_t kb2[2] = { *(const uint32_t*)&Ksm[base],
                                    *(const uint32_t*)&Ksm[base + 8] };
                mma_fp16(sc[nt], qh[kk], kb2);
            }
        }

        #pragma unroll
        for (int nt = 0; nt < 8; nt++) {
            float2 mv = *(const float2*)&mb[bf][nt * 8 + 2 * tg];
            sc[nt][0] += mv.x; sc[nt][1] += mv.y;
            sc[nt][2] += mv.x; sc[nt][3] += mv.y;
        }

        #pragma unroll
        for (int r = 0; r < 2; r++) {
            float mx = -1e30f;
            #pragma unroll
            for (int nt = 0; nt < 8; nt++)
                mx = fmaxf(mx, fmaxf(sc[nt][2 * r], sc[nt][2 * r + 1]));
            mx = fmaxf(mx, __shfl_xor_sync(0xffffffffu, mx, 1));
            mx = fmaxf(mx, __shfl_xor_sync(0xffffffffu, mx, 2));
            const float mn = fmaxf(mrun[r], mx);
            float sum = 0.f;
            #pragma unroll
            for (int nt = 0; nt < 8; nt++) {
                float p0 = ex2f(sc[nt][2 * r]     - mn);
                float p1 = ex2f(sc[nt][2 * r + 1] - mn);
                sc[nt][2 * r] = p0; sc[nt][2 * r + 1] = p1;
                sum += p0 + p1;
            }
            sum += __shfl_xor_sync(0xffffffffu, sum, 1);
            sum += __shfl_xor_sync(0xffffffffu, sum, 2);
            const float al = ex2f(mrun[r] - mn);
            lrun[r] = lrun[r] * al + sum;
            mrun[r] = mn;
            #pragma unroll
            for (int nt = 0; nt < 8; nt++) {
                o[nt][2 * r]     *= al;
                o[nt][2 * r + 1] *= al;
            }
        }

        #pragma unroll
        for (int kk = 0; kk < 4; kk++) {
            uint32_t ph[4];
            ph[0] = pack_h2(sc[2 * kk][0],     sc[2 * kk][1]);
            ph[1] = pack_h2(sc[2 * kk][2],     sc[2 * kk][3]);
            ph[2] = pack_h2(sc[2 * kk + 1][0], sc[2 * kk + 1][1]);
            ph[3] = pack_h2(sc[2 * kk + 1][2], sc[2 * kk + 1][3]);
            #pragma unroll
            for (int nt = 0; nt < 8; nt++) {
                const int base = (nt * 8 + g) * KV_STRIDE + kk * 16 + 2 * tg;
                uint32_t v2[2] = { *(const uint32_t*)&VTs[base],
                                   *(const uint32_t*)&VTs[base + 8] };
                mma_fp16(o[nt], ph, v2);
            }
        }
    }

    // ---- normalize + split fp16 hi/lo + write 64-row A-frag layout ----
    const float inv0 = 1.0f / lrun[0];
    const float inv1 = 1.0f / lrun[1];
    const int m_lo = b * NS + q0 + wid * 16 + g;
    const int m_hi = m_lo + 8;
    uint32_t* aoh32 = (uint32_t*)g_aoh;
    uint32_t* aol32 = (uint32_t*)g_aol;
    #pragma unroll
    for (int nt = 0; nt < 8; nt++) {
        const int col = h * 64 + nt * 8 + 2 * tg;
        uint32_t hi, lo;
        split2h(o[nt][0] * inv0, o[nt][1] * inv0, hi, lo);
        size_t off = af16_off(m_lo, col);
        aoh32[off] = hi; aol32[off] = lo;
        split2h(o[nt][2] * inv1, o[nt][3] * inv1, hi, lo);
        off = af16_off(m_hi, col);
        aoh32[off] = hi; aol32[off] = lo;
    }
}

// ---------------------------------------------------------------------------
extern "C" void kernel_launch(void* const* d_in, const int* in_sizes, int n_in,
                              void* d_out, int out_size)
{
    const float* hs  = (const float*)d_in[0];
    const int*   msk = (const int*)  d_in[1];
    const float* Wq  = (const float*)d_in[2];
    const float* bq  = (const float*)d_in[3];
    const float* Wk  = (const float*)d_in[4];
    const float* bk  = (const float*)d_in[5];
    const float* Wv  = (const float*)d_in[6];
    const float* bv  = (const float*)d_in[7];
    const float* emo = (const float*)d_in[8];
    const float* Wo  = (const float*)d_in[9];
    const float* bo  = (const float*)d_in[10];
    float* out = (float*)d_out;

    cudaFuncSetAttribute(qkv_gemm, cudaFuncAttributeMaxDynamicSharedMemorySize, GEMM_SMEM);
    cudaFuncSetAttribute(out_gemm, cudaFuncAttributeMaxDynamicSharedMemorySize, GEMM_SMEM);
    cudaFuncSetAttribute(attn_kernel, cudaFuncAttributeMaxDynamicSharedMemorySize, ATT_SMEM);

    dim3 gr(128, 5);
    round_prep<<<gr, 256>>>(hs, Wq, Wk, Wv, Wo);

    dim3 gqkv(ND / 128, MT / 64, 3);
    qkv_gemm<<<gqkv, 128, GEMM_SMEM>>>(bq, bk, bv, emo);

    dim3 gatt(NS / 128, NB * NH);
    attn_kernel<<<gatt, 256, ATT_SMEM>>>(msk);

    dim3 gout(ND / 128, MT / 64);
    out_gemm<<<gout, 128, GEMM_SMEM>>>(bo, out);
}

// round 14
// speedup vs baseline: 1.0723x; 1.0194x over previous
#include <cuda_runtime.h>
#include <cuda_bf16.h>
#include <cuda_fp16.h>
#include <cstdint>
#include <math.h>

#define NB 2
#define NS 2048
#define ND 1024
#define NH 16
#define NDH 64
#define MT (NB*NS)          // 4096 rows in all GEMMs
#define LOG2E 1.4426950408889634f

// Scratch (allocation-free rule: __device__ globals)
__device__ float g_q [NB*NH*NS*NDH];   // [B,H,S,DH] fp32 (row-major)
// GEMM operands, fp16 fragment layouts:
//   A-layout: 64-row tiles [mb64][kb][2048 halves], B-layout [nb][kb][4096 halves]
__device__ unsigned short g_xh [MT*ND];   // X hi
__device__ unsigned short g_xl [MT*ND];   // X lo
__device__ unsigned short g_wq16[ND*ND];  // 32*W in fp16, B-frag layout
__device__ unsigned short g_wk16[ND*ND];
__device__ unsigned short g_wv16[ND*ND];
__device__ unsigned short g_wo16[ND*ND];
__device__ unsigned short g_aoh[MT*ND];   // attention out hi (A-frag layout)
__device__ unsigned short g_aol[MT*ND];   // attention out lo
// K: fp16 (natural [bh][s][d]); V: fp16 (transposed [bh][d][s])
__device__ unsigned short g_kf16 [NB*NH*NS*NDH];
__device__ unsigned short g_vt16 [NB*NH*NS*NDH];

// ===========================================================================
// Helpers
// ===========================================================================
__device__ __forceinline__ uint32_t smem_u32(const void* p) {
    uint32_t a;
    asm("{ .reg .u64 t; cvta.to.shared.u64 t, %1; cvt.u32.u64 %0, t; }"
        : "=r"(a) : "l"(p));
    return a;
}

__device__ __forceinline__ float ex2f(float x) {      // bare MUFU.EX2, ftz
    float y;
    asm("ex2.approx.ftz.f32 %0, %1;" : "=f"(y) : "f"(x));
    return y;
}

__device__ __forceinline__ void mma_fp16(float (&c)[4],
                                         const uint32_t (&a)[4],
                                         const uint32_t (&b)[2]) {
    asm volatile(
        "mma.sync.aligned.m16n8k16.row.col.f32.f16.f16.f32 "
        "{%0,%1,%2,%3}, {%4,%5,%6,%7}, {%8,%9}, {%0,%1,%2,%3};"
        : "+f"(c[0]), "+f"(c[1]), "+f"(c[2]), "+f"(c[3])
        : "r"(a[0]), "r"(a[1]), "r"(a[2]), "r"(a[3]), "r"(b[0]), "r"(b[1]));
}

__device__ __forceinline__ uint32_t pack_h2(float x0, float x1) {
    __half2 h = __floats2half2_rn(x0, x1);
    return *(uint32_t*)&h;
}

// Split a pair of floats into packed fp16x2 hi + lo
__device__ __forceinline__ void split2h(float x0, float x1,
                                        uint32_t& hi, uint32_t& lo) {
    __half2 h = __floats2half2_rn(x0, x1);
    float2 hf = __half22float2(h);
    __half2 l = __floats2half2_rn(x0 - hf.x, x1 - hf.y);
    hi = *(uint32_t*)&h;
    lo = *(uint32_t*)&l;
}

#define CP16(dst, src) \
    asm volatile("cp.async.cg.shared.global [%0], [%1], 16;" \
                 :: "r"(dst), "l"(src))
#define CP_COMMIT() asm volatile("cp.async.commit_group;" ::: "memory")
#define CP_WAIT1()  asm volatile("cp.async.wait_group 1;" ::: "memory")
#define CP_WAIT0()  asm volatile("cp.async.wait_group 0;" ::: "memory")

// A-fragment (64-row tiles) u32 index for element pair (m, k even):
//   tile 1024 u32; u32 = ((c*4+mf)*32 + g*4+tg)*4 + khalf8*2 + mhalf
__device__ __forceinline__ size_t af16_off(int m, int k) {
    const int mb = m >> 6, kb = k >> 5, c = (k >> 4) & 1;
    const int mf = (m >> 4) & 3, g = m & 7, mhalf = (m >> 3) & 1;
    const int tg = (k >> 1) & 3, khalf8 = (k >> 3) & 1;
    return ((size_t)(mb * 32 + kb)) * 1024
         + (size_t)((((c * 4 + mf) * 32 + g * 4 + tg) * 4) + khalf8 * 2 + mhalf);
}

#define STAGE_B   16384            // A_hi 4K + A_lo 4K + B 8K
#define GEMM_SMEM (3 * STAGE_B)    // 49152, 3-stage

// ---------------------------------------------------------------------------
// fp16 2-term GEMM core, 128 threads (4 warps), CTA tile 64m x 128n.
// Warp w owns 64m x 32n (wn = wid). 3-stage, one barrier per k-tile.
// C = (A_hi + A_lo) * B, fp32 accum; caller scales by 1/32 (B = 32*W).
// ---------------------------------------------------------------------------
__device__ __forceinline__ void gemm_f16_core(
    const unsigned short* __restrict__ Ah,
    const unsigned short* __restrict__ Al,
    const unsigned short* __restrict__ Bf,
    char* sm, int mblk, int nblk, float (&acc)[4][4][4])
{
    const int tid  = threadIdx.x;
    const int wn   = tid >> 5, lane = tid & 31;

    #pragma unroll
    for (int mt = 0; mt < 4; mt++)
        #pragma unroll
        for (int nt = 0; nt < 4; nt++)
            #pragma unroll
            for (int i = 0; i < 4; i++) acc[mt][nt][i] = 0.f;

    const uint32_t sm_u = smem_u32(sm);

    auto issue_tile = [&](int kt, int bf) {
        const unsigned short* sAh = Ah + ((size_t)(mblk * 32 + kt)) * 2048;
        const unsigned short* sAl = Al + ((size_t)(mblk * 32 + kt)) * 2048;
        const unsigned short* sB  = Bf + ((size_t)(nblk * 32 + kt)) * 4096;
        const uint32_t st = sm_u + bf * STAGE_B;
        #pragma unroll
        for (int i = 0; i < 2; i++) {
            const int f = tid + i * 128;
            CP16(st +        f * 16, sAh + f * 8);
            CP16(st + 4096 + f * 16, sAl + f * 8);
        }
        #pragma unroll
        for (int i = 0; i < 4; i++) {
            const int f = tid + i * 128;
            CP16(st + 8192 + f * 16, sB + f * 8);
        }
        CP_COMMIT();
    };

    issue_tile(0, 0);
    issue_tile(1, 1);

    for (int kt = 0; kt < 32; kt++) {
        const int bf = kt % 3;
        if (kt == 31) CP_WAIT0(); else CP_WAIT1();
        __syncthreads();
        if (kt + 2 < 32) issue_tile(kt + 2, (kt + 2) % 3);

        const uint4* Ah4 = (const uint4*)(sm + bf * STAGE_B);
        const uint4* Al4 = (const uint4*)(sm + bf * STAGE_B + 4096);
        const uint2* B2  = (const uint2*)(sm + bf * STAGE_B + 8192);

        #pragma unroll
        for (int c = 0; c < 2; c++) {
            uint2 bv[4];
            #pragma unroll
            for (int nt = 0; nt < 4; nt++)
                bv[nt] = B2[(c * 16 + wn * 4 + nt) * 32 + lane];

            uint32_t a[4][4];
            #pragma unroll
            for (int mt = 0; mt < 4; mt++) {
                uint4 t = Ah4[(c * 4 + mt) * 32 + lane];
                a[mt][0] = t.x; a[mt][1] = t.y; a[mt][2] = t.z; a[mt][3] = t.w;
            }
            #pragma unroll
            for (int mt = 0; mt < 4; mt++)
                #pragma unroll
                for (int nt = 0; nt < 4; nt++) {
                    uint32_t b2[2] = { bv[nt].x, bv[nt].y };
                    mma_fp16(acc[mt][nt], a[mt], b2);
                }
            #pragma unroll
            for (int mt = 0; mt < 4; mt++) {
                uint4 t = Al4[(c * 4 + mt) * 32 + lane];
                a[mt][0] = t.x; a[mt][1] = t.y; a[mt][2] = t.z; a[mt][3] = t.w;
            }
            #pragma unroll
            for (int mt = 0; mt < 4; mt++)
                #pragma unroll
                for (int nt = 0; nt < 4; nt++) {
                    uint32_t b2[2] = { bv[nt].x, bv[nt].y };
                    mma_fp16(acc[mt][nt], a[mt], b2);
                }
        }
    }
    __syncthreads();   // protect smem reuse by epilogue
}

// ---------------------------------------------------------------------------
// Round prep: X -> fp16 hi/lo (64-row A-frag tiles); W -> fp16 of 32*W (B-frag).
// ---------------------------------------------------------------------------
__global__ __launch_bounds__(256) void round_prep(
    const float* __restrict__ X,  const float* __restrict__ Wq,
    const float* __restrict__ Wk, const float* __restrict__ Wv,
    const float* __restrict__ Wo)
{
    const int z = blockIdx.y;
    if (z == 0) {
        for (int t = blockIdx.x * 256 + threadIdx.x; t < MT * ND / 2;
             t += gridDim.x * 256) {
            const int tile = t >> 10, w = t & 1023;
            const int j = w & 3, lane = (w >> 2) & 31, grp = w >> 7;
            const int c = grp >> 2, mf = grp & 3;
            const int mb = tile >> 5, kb = tile & 31;
            const int g = lane >> 2, tg = lane & 3;
            const int m = mb * 64 + mf * 16 + (j & 1) * 8 + g;
            const int k = kb * 32 + c * 16 + (j >> 1) * 8 + 2 * tg;
            uint32_t hi, lo;
            split2h(X[(size_t)m * ND + k], X[(size_t)m * ND + k + 1], hi, lo);
            ((uint32_t*)g_xh)[t] = hi;
            ((uint32_t*)g_xl)[t] = lo;
        }
    } else {
        const float* s = (z == 1) ? Wq : (z == 2) ? Wk : (z == 3) ? Wv : Wo;
        unsigned short* d = (z == 1) ? g_wq16 : (z == 2) ? g_wk16
                          : (z == 3) ? g_wv16 : g_wo16;
        for (int t = blockIdx.x * 256 + threadIdx.x; t < ND * ND / 2;
             t += gridDim.x * 256) {
            const int tile = t >> 11, w = t & 2047;
            const int jj = w & 1, lane = (w >> 1) & 31;
            const int nf = (w >> 6) & 15, c = (w >> 10) & 1;
            const int nb = tile >> 5, kb = tile & 31;
            const int g = lane >> 2, tg = lane & 3;
            const int k = kb * 32 + c * 16 + jj * 8 + 2 * tg;
            const int n = nb * 128 + nf * 8 + g;
            ((uint32_t*)d)[t] = pack_h2(32.f * s[(size_t)k * ND + n],
                                        32.f * s[(size_t)(k + 1) * ND + n]);
        }
    }
}

// ---------------------------------------------------------------------------
// QKV projection (128 threads, 64x128 tile): z=0 -> Q fp32 (+bias+emotion);
// z=1 -> K fp16 [bh][s][d]; z=2 -> V fp16 transposed [bh][d][s].
// Epilogue scales acc by 1/32 (B = 32*W).
// ---------------------------------------------------------------------------
__global__ __launch_bounds__(128, 4) void qkv_gemm(
    const float* __restrict__ bq, const float* __restrict__ bk,
    const float* __restrict__ bv, const float* __restrict__ emo)
{
    extern __shared__ char sm[];
    const int z = blockIdx.z;
    const unsigned short* W = (z == 0) ? g_wq16 : (z == 1) ? g_wk16 : g_wv16;
    const float* bias = (z == 0) ? bq : (z == 1) ? bk : bv;

    const int m0 = blockIdx.y * 64, n0 = blockIdx.x * 128;
    float acc[4][4][4];
    gemm_f16_core(g_xh, g_xl, W, sm, blockIdx.y, blockIdx.x, acc);

    const int tid = threadIdx.x, wn = tid >> 5, lane = tid & 31;
    const int g = lane >> 2, tg = lane & 3;
    const float sc = 0.03125f;

    if (z == 0) {
        #pragma unroll
        for (int mt = 0; mt < 4; mt++) {
            #pragma unroll
            for (int nt = 0; nt < 4; nt++) {
                const int n = n0 + wn * 32 + nt * 8 + 2 * tg;
                const int h = n >> 6, dh = n & 63;
                float b0 = bias[n]     + emo[n];
                float b1 = bias[n + 1] + emo[n + 1];
                #pragma unroll
                for (int half = 0; half < 2; half++) {
                    const int r = m0 + mt * 16 + g + half * 8;
                    const int bb = r >> 11, s = r & (NS - 1);
                    float2 v = make_float2(acc[mt][nt][2 * half] * sc + b0,
                                           acc[mt][nt][2 * half + 1] * sc + b1);
                    *(float2*)&g_q[(((size_t)bb * NH + h) * NS + s) * NDH + dh] = v;
                }
            }
        }
    } else if (z == 1) {
        #pragma unroll
        for (int mt = 0; mt < 4; mt++) {
            #pragma unroll
            for (int nt = 0; nt < 4; nt++) {
                const int n = n0 + wn * 32 + nt * 8 + 2 * tg;
                const int h = n >> 6, dh = n & 63;
                float b0 = bias[n], b1 = bias[n + 1];
                #pragma unroll
                for (int half = 0; half < 2; half++) {
                    const int r = m0 + mt * 16 + g + half * 8;
                    const int bb = r >> 11, s = r & (NS - 1);
                    uint32_t v = pack_h2(acc[mt][nt][2 * half] * sc + b0,
                                         acc[mt][nt][2 * half + 1] * sc + b1);
                    *(uint32_t*)&g_kf16[(((size_t)bb * NH + h) * NS + s) * NDH + dh] = v;
                }
            }
        }
    } else {
        // V fp16 transposed via smem: vt[nl][sl], nl 0..127, sl 0..63, stride 72
        unsigned short* vt = (unsigned short*)sm;
        #pragma unroll
        for (int mt = 0; mt < 4; mt++) {
            #pragma unroll
            for (int nt = 0; nt < 4; nt++) {
                const int nl = wn * 32 + nt * 8 + 2 * tg;
                float b0 = bias[n0 + nl], b1 = bias[n0 + nl + 1];
                #pragma unroll
                for (int half = 0; half < 2; half++) {
                    const int sl = mt * 16 + g + half * 8;
                    vt[nl * 72 + sl]       = __half_as_ushort(
                        __float2half_rn(acc[mt][nt][2 * half] * sc + b0));
                    vt[(nl + 1) * 72 + sl] = __half_as_ushort(
                        __float2half_rn(acc[mt][nt][2 * half + 1] * sc + b1));
                }
            }
        }
        __syncthreads();
        const int bb = m0 >> 11, sbase = m0 & (NS - 1);
        for (int i = tid; i < 128 * 32; i += 128) {
            const int nl = i >> 5, s2 = (i & 31) * 2;
            const int n = n0 + nl, h = n >> 6, dh = n & 63;
            *(uint32_t*)&g_vt16[(((size_t)bb * NH + h) * NDH + dh) * NS + sbase + s2] =
                *(const uint32_t*)&vt[nl * 72 + s2];
        }
    }
}

// ---------------------------------------------------------------------------
// Output projection (128 threads): (g_aoh+g_aol) @ g_wo16 -> out = acc/32 + bo
// ---------------------------------------------------------------------------
__global__ __launch_bounds__(128, 4) void out_gemm(
    const float* __restrict__ bo, float* __restrict__ out)
{
    extern __shared__ char sm[];
    const int m0 = blockIdx.y * 64, n0 = blockIdx.x * 128;
    float acc[4][4][4];
    gemm_f16_core(g_aoh, g_aol, g_wo16, sm, blockIdx.y, blockIdx.x, acc);

    const int tid = threadIdx.x, wn = tid >> 5, lane = tid & 31;
    const int g = lane >> 2, tg = lane & 3;
    const float sc = 0.03125f;

    #pragma unroll
    for (int mt = 0; mt < 4; mt++) {
        #pragma unroll
        for (int nt = 0; nt < 4; nt++) {
            const int n = n0 + wn * 32 + nt * 8 + 2 * tg;
            float b0 = bo[n], b1 = bo[n + 1];
            #pragma unroll
            for (int half = 0; half < 2; half++) {
                const int r = m0 + mt * 16 + g + half * 8;
                float2 v = make_float2(acc[mt][nt][2 * half] * sc + b0,
                                       acc[mt][nt][2 * half + 1] * sc + b1);
                *(float2*)&out[(size_t)r * ND + n] = v;
            }
        }
    }
}

// ---------------------------------------------------------------------------
// Flash attention, 128 threads / 64 q-rows / 4 CTAs per SM.
// Warp w owns rows q0 + w*16 .. +15 (fragment structure unchanged).
// S = QK^T fp16, O = PV fp16, log2 softmax; 3-stage cp.async, 1 barrier/tile.
// Epilogue writes g_aoh/g_aol (fp16 hi/lo, 64-row A-frag layout).
// ---------------------------------------------------------------------------
#define KV_STRIDE 72
#define ARR_B     (64 * 144)
#define ATT_STAGE (2 * ARR_B)
#define ATT_SMEM  (3 * ATT_STAGE)   // 55296

__global__ __launch_bounds__(128, 4) void attn_kernel(const int* __restrict__ mask)
{
    extern __shared__ char att_sm[];
    __shared__ float mb[3][64];

    const int bh = blockIdx.y;
    const int b  = bh >> 4;
    const int h  = bh & 15;
    const int q0 = blockIdx.x * 64;
    const float* Qp = g_q + (size_t)bh * NS * NDH;
    const unsigned short* KF = g_kf16 + (size_t)bh * NS * NDH;   // [s][d] fp16
    const unsigned short* VT = g_vt16 + (size_t)bh * NS * NDH;   // [d][s] fp16
    const int* mrow = mask + b * NS;

    const int tid = threadIdx.x, wid = tid >> 5, lane = tid & 31;
    const int g = lane >> 2, tg = lane & 3;
    const uint32_t sb = smem_u32(att_sm);

    auto issue = [&](int kb, int bf) {
        const int k0g = kb * 64;
        const uint32_t st = sb + bf * ATT_STAGE;
        #pragma unroll
        for (int i = 0; i < 4; i++) {
            int f = tid + i * 128;
            int row = f >> 3, q = f & 7;
            CP16(st + 0 * ARR_B + row * 144 + q * 16,
                 KF + (size_t)(k0g + row) * NDH + q * 8);
            CP16(st + 1 * ARR_B + row * 144 + q * 16,
                 VT + (size_t)row * NS + k0g + q * 8);
        }
        CP_COMMIT();
    };

    const float qs = 0.125f * LOG2E;
    uint32_t qh[4][4];
    {
        const float* q0p = Qp + (size_t)(q0 + wid * 16 + g) * NDH;
        const float* q1p = q0p + 8 * NDH;
        #pragma unroll
        for (int kk = 0; kk < 4; kk++) {
            float2 x;
            x = *(const float2*)(q0p + kk * 16 + 2 * tg);
            qh[kk][0] = pack_h2(qs * x.x, qs * x.y);
            x = *(const float2*)(q1p + kk * 16 + 2 * tg);
            qh[kk][1] = pack_h2(qs * x.x, qs * x.y);
            x = *(const float2*)(q0p + kk * 16 + 2 * tg + 8);
            qh[kk][2] = pack_h2(qs * x.x, qs * x.y);
            x = *(const float2*)(q1p + kk * 16 + 2 * tg + 8);
            qh[kk][3] = pack_h2(qs * x.x, qs * x.y);
        }
    }

    float o[8][4];
    #pragma unroll
    for (int nt = 0; nt < 8; nt++)
        #pragma unroll
        for (int i = 0; i < 4; i++) o[nt][i] = 0.f;
    float mrun[2] = {-1e30f, -1e30f}, lrun[2] = {0.f, 0.f};

    issue(0, 0);
    issue(1, 1);
    if (tid < 64) {
        mb[0][tid] = mrow[tid]      ? 0.f : -1e30f;
        mb[1][tid] = mrow[64 + tid] ? 0.f : -1e30f;
    }

    for (int kb = 0; kb < NS / 64; kb++) {
        const int bf = kb % 3;
        if (kb == NS / 64 - 1) CP_WAIT0(); else CP_WAIT1();
        __syncthreads();
        if (kb + 2 < NS / 64) {
            issue(kb + 2, (kb + 2) % 3);
            if (tid < 64)
                mb[(kb + 2) % 3][tid] = mrow[(kb + 2) * 64 + tid] ? 0.f : -1e30f;
        }

        const unsigned short* Ksm = (const unsigned short*)(att_sm + bf * ATT_STAGE);
        const unsigned short* VTs = Ksm + 64 * KV_STRIDE;

        float sc[8][4];
        #pragma unroll
        for (int nt = 0; nt < 8; nt++)
            #pragma unroll
            for (int i = 0; i < 4; i++) sc[nt][i] = 0.f;

        #pragma unroll
        for (int kk = 0; kk < 4; kk++) {
            #pragma unroll
            for (int nt = 0; nt < 8; nt++) {
                const int base = (nt * 8 + g) * KV_STRIDE + kk * 16 + 2 * tg;
                uint32_t kb2[2] = { *(const uint32_t*)&Ksm[base],
                                    *(const uint32_t*)&Ksm[base + 8] };
                mma_fp16(sc[nt], qh[kk], kb2);
            }
        }

        #pragma unroll
        for (int nt = 0; nt < 8; nt++) {
            float2 mv = *(const float2*)&mb[bf][nt * 8 + 2 * tg];
            sc[nt][0] += mv.x; sc[nt][1] += mv.y;
            sc[nt][2] += mv.x; sc[nt][3] += mv.y;
        }

        #pragma unroll
        for (int r = 0; r < 2; r++) {
            float mx = -1e30f;
            #pragma unroll
            for (int nt = 0; nt < 8; nt++)
                mx = fmaxf(mx, fmaxf(sc[nt][2 * r], sc[nt][2 * r + 1]));
            mx = fmaxf(mx, __shfl_xor_sync(0xffffffffu, mx, 1));
            mx = fmaxf(mx, __shfl_xor_sync(0xffffffffu, mx, 2));
            const float mn = fmaxf(mrun[r], mx);
            float sum = 0.f;
            #pragma unroll
            for (int nt = 0; nt < 8; nt++) {
                float p0 = ex2f(sc[nt][2 * r]     - mn);
                float p1 = ex2f(sc[nt][2 * r + 1] - mn);
                sc[nt][2 * r] = p0; sc[nt][2 * r + 1] = p1;
                sum += p0 + p1;
            }
            sum += __shfl_xor_sync(0xffffffffu, sum, 1);
            sum += __shfl_xor_sync(0xffffffffu, sum, 2);
            const float al = ex2f(mrun[r] - mn);
            lrun[r] = lrun[r] * al + sum;
            mrun[r] = mn;
            #pragma unroll
            for (int nt = 0; nt < 8; nt++) {
                o[nt][2 * r]     *= al;
                o[nt][2 * r + 1] *= al;
            }
        }

        #pragma unroll
        for (int kk = 0; kk < 4; kk++) {
            uint32_t ph[4];
            ph[0] = pack_h2(sc[2 * kk][0],     sc[2 * kk][1]);
            ph[1] = pack_h2(sc[2 * kk][2],     sc[2 * kk][3]);
            ph[2] = pack_h2(sc[2 * kk + 1][0], sc[2 * kk + 1][1]);
            ph[3] = pack_h2(sc[2 * kk + 1][2], sc[2 * kk + 1][3]);
            #pragma unroll
            for (int nt = 0; nt < 8; nt++) {
                const int base = (nt * 8 + g) * KV_STRIDE + kk * 16 + 2 * tg;
                uint32_t v2[2] = { *(const uint32_t*)&VTs[base],
                                   *(const uint32_t*)&VTs[base + 8] };
                mma_fp16(o[nt], ph, v2);
            }
        }
    }

    // ---- normalize + split fp16 hi/lo + write 64-row A-frag layout ----
    const float inv0 = 1.0f / lrun[0];
    const float inv1 = 1.0f / lrun[1];
    const int m_lo = b * NS + q0 + wid * 16 + g;
    const int m_hi = m_lo + 8;
    uint32_t* aoh32 = (uint32_t*)g_aoh;
    uint32_t* aol32 = (uint32_t*)g_aol;
    #pragma unroll
    for (int nt = 0; nt < 8; nt++) {
        const int col = h * 64 + nt * 8 + 2 * tg;
        uint32_t hi, lo;
        split2h(o[nt][0] * inv0, o[nt][1] * inv0, hi, lo);
        size_t off = af16_off(m_lo, col);
        aoh32[off] = hi; aol32[off] = lo;
        split2h(o[nt][2] * inv1, o[nt][3] * inv1, hi, lo);
        off = af16_off(m_hi, col);
        aoh32[off] = hi; aol32[off] = lo;
    }
}

// ---------------------------------------------------------------------------
extern "C" void kernel_launch(void* const* d_in, const int* in_sizes, int n_in,
                              void* d_out, int out_size)
{
    const float* hs  = (const float*)d_in[0];
    const int*   msk = (const int*)  d_in[1];
    const float* Wq  = (const float*)d_in[2];
    const float* bq  = (const float*)d_in[3];
    const float* Wk  = (const float*)d_in[4];
    const float* bk  = (const float*)d_in[5];
    const float* Wv  = (const float*)d_in[6];
    const float* bv  = (const float*)d_in[7];
    const float* emo = (const float*)d_in[8];
    const float* Wo  = (const float*)d_in[9];
    const float* bo  = (const float*)d_in[10];
    float* out = (float*)d_out;

    cudaFuncSetAttribute(qkv_gemm, cudaFuncAttributeMaxDynamicSharedMemorySize, GEMM_SMEM);
    cudaFuncSetAttribute(out_gemm, cudaFuncAttributeMaxDynamicSharedMemorySize, GEMM_SMEM);
    cudaFuncSetAttribute(attn_kernel, cudaFuncAttributeMaxDynamicSharedMemorySize, ATT_SMEM);

    dim3 gr(128, 5);
    round_prep<<<gr, 256>>>(hs, Wq, Wk, Wv, Wo);

    dim3 gqkv(ND / 128, MT / 64, 3);
    qkv_gemm<<<gqkv, 128, GEMM_SMEM>>>(bq, bk, bv, emo);

    dim3 gatt(NS / 64, NB * NH);
    attn_kernel<<<gatt, 128, ATT_SMEM>>>(msk);

    dim3 gout(ND / 128, MT / 64);
    out_gemm<<<gout, 128, GEMM_SMEM>>>(bo, out);
}

// round 15
// speedup vs baseline: 1.1475x; 1.0702x over previous
#include <cuda_runtime.h>
#include <cuda_bf16.h>
#include <cuda_fp16.h>
#include <cstdint>
#include <math.h>

#define NB 2
#define NS 2048
#define ND 1024
#define NH 16
#define NDH 64
#define MT (NB*NS)          // 4096 rows in all GEMMs
#define LOG2E 1.4426950408889634f

// Scratch (allocation-free rule: __device__ globals)
__device__ float g_q [NB*NH*NS*NDH];   // [B,H,S,DH] fp32 (row-major)
// GEMM operands, fp16 fragment layouts:
//   A-layout: 64-row tiles [mb64][kb][2048 halves], B-layout [nb][kb][4096 halves]
__device__ unsigned short g_xh [MT*ND];   // X hi
__device__ unsigned short g_xl [MT*ND];   // X lo
__device__ unsigned short g_wq16[ND*ND];  // 32*W in fp16, B-frag layout
__device__ unsigned short g_wk16[ND*ND];
__device__ unsigned short g_wv16[ND*ND];
__device__ unsigned short g_wo16[ND*ND];
__device__ unsigned short g_aoh[MT*ND];   // attention out hi (A-frag layout)
__device__ unsigned short g_aol[MT*ND];   // attention out lo
// K tiles in B-frag layout: [bh][kt][4096 halves] (64 kpos x 64 d per tile)
// V^T tiles in B-frag layout: [bh][kt][4096 halves] (64 d x 64 kpos per tile)
__device__ unsigned short g_kt16 [NB*NH*NS*NDH];
__device__ unsigned short g_vt16 [NB*NH*NS*NDH];

// ===========================================================================
// Helpers
// ===========================================================================
__device__ __forceinline__ uint32_t smem_u32(const void* p) {
    uint32_t a;
    asm("{ .reg .u64 t; cvta.to.shared.u64 t, %1; cvt.u32.u64 %0, t; }"
        : "=r"(a) : "l"(p));
    return a;
}

__device__ __forceinline__ float ex2f(float x) {      // bare MUFU.EX2, ftz
    float y;
    asm("ex2.approx.ftz.f32 %0, %1;" : "=f"(y) : "f"(x));
    return y;
}

__device__ __forceinline__ void mma_fp16(float (&c)[4],
                                         const uint32_t (&a)[4],
                                         const uint32_t (&b)[2]) {
    asm volatile(
        "mma.sync.aligned.m16n8k16.row.col.f32.f16.f16.f32 "
        "{%0,%1,%2,%3}, {%4,%5,%6,%7}, {%8,%9}, {%0,%1,%2,%3};"
        : "+f"(c[0]), "+f"(c[1]), "+f"(c[2]), "+f"(c[3])
        : "r"(a[0]), "r"(a[1]), "r"(a[2]), "r"(a[3]), "r"(b[0]), "r"(b[1]));
}

__device__ __forceinline__ uint32_t pack_h2(float x0, float x1) {
    __half2 h = __floats2half2_rn(x0, x1);
    return *(uint32_t*)&h;
}

// Split a pair of floats into packed fp16x2 hi + lo
__device__ __forceinline__ void split2h(float x0, float x1,
                                        uint32_t& hi, uint32_t& lo) {
    __half2 h = __floats2half2_rn(x0, x1);
    float2 hf = __half22float2(h);
    __half2 l = __floats2half2_rn(x0 - hf.x, x1 - hf.y);
    hi = *(uint32_t*)&h;
    lo = *(uint32_t*)&l;
}

#define CP16(dst, src) \
    asm volatile("cp.async.cg.shared.global [%0], [%1], 16;" \
                 :: "r"(dst), "l"(src))
#define CP_COMMIT() asm volatile("cp.async.commit_group;" ::: "memory")
#define CP_WAIT1()  asm volatile("cp.async.wait_group 1;" ::: "memory")
#define CP_WAIT0()  asm volatile("cp.async.wait_group 0;" ::: "memory")

// A-fragment (64-row tiles) u32 index for element pair (m, k even)
__device__ __forceinline__ size_t af16_off(int m, int k) {
    const int mb = m >> 6, kb = k >> 5, c = (k >> 4) & 1;
    const int mf = (m >> 4) & 3, g = m & 7, mhalf = (m >> 3) & 1;
    const int tg = (k >> 1) & 3, khalf8 = (k >> 3) & 1;
    return ((size_t)(mb * 32 + kb)) * 1024
         + (size_t)((((c * 4 + mf) * 32 + g * 4 + tg) * 4) + khalf8 * 2 + mhalf);
}

// B-fragment 64x64 tile u32 index for element pair (row, col even):
//   idx = ((kk*8 + nt)*32 + g*4 + tg)*2 + khalf
//   nt = row>>3, g = row&7; kk = col>>4, khalf = (col>>3)&1, tg = (col>>1)&3
__device__ __forceinline__ int bfrag64_off(int row, int col) {
    const int nt = row >> 3, g = row & 7;
    const int kk = col >> 4, khalf = (col >> 3) & 1, tg = (col >> 1) & 3;
    return (((kk * 8 + nt) * 32 + g * 4 + tg) * 2) + khalf;
}

#define STAGE_B   16384            // A_hi 4K + A_lo 4K + B 8K
#define GEMM_SMEM (3 * STAGE_B)    // 49152, 3-stage

// ---------------------------------------------------------------------------
// fp16 2-term GEMM core, 128 threads (4 warps), CTA tile 64m x 128n.
// ---------------------------------------------------------------------------
__device__ __forceinline__ void gemm_f16_core(
    const unsigned short* __restrict__ Ah,
    const unsigned short* __restrict__ Al,
    const unsigned short* __restrict__ Bf,
    char* sm, int mblk, int nblk, float (&acc)[4][4][4])
{
    const int tid  = threadIdx.x;
    const int wn   = tid >> 5, lane = tid & 31;

    #pragma unroll
    for (int mt = 0; mt < 4; mt++)
        #pragma unroll
        for (int nt = 0; nt < 4; nt++)
            #pragma unroll
            for (int i = 0; i < 4; i++) acc[mt][nt][i] = 0.f;

    const uint32_t sm_u = smem_u32(sm);

    auto issue_tile = [&](int kt, int bf) {
        const unsigned short* sAh = Ah + ((size_t)(mblk * 32 + kt)) * 2048;
        const unsigned short* sAl = Al + ((size_t)(mblk * 32 + kt)) * 2048;
        const unsigned short* sB  = Bf + ((size_t)(nblk * 32 + kt)) * 4096;
        const uint32_t st = sm_u + bf * STAGE_B;
        #pragma unroll
        for (int i = 0; i < 2; i++) {
            const int f = tid + i * 128;
            CP16(st +        f * 16, sAh + f * 8);
            CP16(st + 4096 + f * 16, sAl + f * 8);
        }
        #pragma unroll
        for (int i = 0; i < 4; i++) {
            const int f = tid + i * 128;
            CP16(st + 8192 + f * 16, sB + f * 8);
        }
        CP_COMMIT();
    };

    issue_tile(0, 0);
    issue_tile(1, 1);

    for (int kt = 0; kt < 32; kt++) {
        const int bf = kt % 3;
        if (kt == 31) CP_WAIT0(); else CP_WAIT1();
        __syncthreads();
        if (kt + 2 < 32) issue_tile(kt + 2, (kt + 2) % 3);

        const uint4* Ah4 = (const uint4*)(sm + bf * STAGE_B);
        const uint4* Al4 = (const uint4*)(sm + bf * STAGE_B + 4096);
        const uint2* B2  = (const uint2*)(sm + bf * STAGE_B + 8192);

        #pragma unroll
        for (int c = 0; c < 2; c++) {
            uint2 bv[4];
            #pragma unroll
            for (int nt = 0; nt < 4; nt++)
                bv[nt] = B2[(c * 16 + wn * 4 + nt) * 32 + lane];

            uint32_t a[4][4];
            #pragma unroll
            for (int mt = 0; mt < 4; mt++) {
                uint4 t = Ah4[(c * 4 + mt) * 32 + lane];
                a[mt][0] = t.x; a[mt][1] = t.y; a[mt][2] = t.z; a[mt][3] = t.w;
            }
            #pragma unroll
            for (int mt = 0; mt < 4; mt++)
                #pragma unroll
                for (int nt = 0; nt < 4; nt++) {
                    uint32_t b2[2] = { bv[nt].x, bv[nt].y };
                    mma_fp16(acc[mt][nt], a[mt], b2);
                }
            #pragma unroll
            for (int mt = 0; mt < 4; mt++) {
                uint4 t = Al4[(c * 4 + mt) * 32 + lane];
                a[mt][0] = t.x; a[mt][1] = t.y; a[mt][2] = t.z; a[mt][3] = t.w;
            }
            #pragma unroll
            for (int mt = 0; mt < 4; mt++)
                #pragma unroll
                for (int nt = 0; nt < 4; nt++) {
                    uint32_t b2[2] = { bv[nt].x, bv[nt].y };
                    mma_fp16(acc[mt][nt], a[mt], b2);
                }
        }
    }
    __syncthreads();   // protect smem reuse by epilogue
}

// ---------------------------------------------------------------------------
// Round prep: X -> fp16 hi/lo (64-row A-frag tiles); W -> fp16 of 32*W (B-frag).
// ---------------------------------------------------------------------------
__global__ __launch_bounds__(256) void round_prep(
    const float* __restrict__ X,  const float* __restrict__ Wq,
    const float* __restrict__ Wk, const float* __restrict__ Wv,
    const float* __restrict__ Wo)
{
    const int z = blockIdx.y;
    if (z == 0) {
        for (int t = blockIdx.x * 256 + threadIdx.x; t < MT * ND / 2;
             t += gridDim.x * 256) {
            const int tile = t >> 10, w = t & 1023;
            const int j = w & 3, lane = (w >> 2) & 31, grp = w >> 7;
            const int c = grp >> 2, mf = grp & 3;
            const int mb = tile >> 5, kb = tile & 31;
            const int g = lane >> 2, tg = lane & 3;
            const int m = mb * 64 + mf * 16 + (j & 1) * 8 + g;
            const int k = kb * 32 + c * 16 + (j >> 1) * 8 + 2 * tg;
            uint32_t hi, lo;
            split2h(X[(size_t)m * ND + k], X[(size_t)m * ND + k + 1], hi, lo);
            ((uint32_t*)g_xh)[t] = hi;
            ((uint32_t*)g_xl)[t] = lo;
        }
    } else {
        const float* s = (z == 1) ? Wq : (z == 2) ? Wk : (z == 3) ? Wv : Wo;
        unsigned short* d = (z == 1) ? g_wq16 : (z == 2) ? g_wk16
                          : (z == 3) ? g_wv16 : g_wo16;
        for (int t = blockIdx.x * 256 + threadIdx.x; t < ND * ND / 2;
             t += gridDim.x * 256) {
            const int tile = t >> 11, w = t & 2047;
            const int jj = w & 1, lane = (w >> 1) & 31;
            const int nf = (w >> 6) & 15, c = (w >> 10) & 1;
            const int nb = tile >> 5, kb = tile & 31;
            const int g = lane >> 2, tg = lane & 3;
            const int k = kb * 32 + c * 16 + jj * 8 + 2 * tg;
            const int n = nb * 128 + nf * 8 + g;
            ((uint32_t*)d)[t] = pack_h2(32.f * s[(size_t)k * ND + n],
                                        32.f * s[(size_t)(k + 1) * ND + n]);
        }
    }
}

// ---------------------------------------------------------------------------
// QKV projection (128 threads, 64x128 tile): z=0 -> Q fp32 (+bias+emotion);
// z=1 -> K fp16 B-frag tiles; z=2 -> V^T fp16 B-frag tiles (via smem).
// Epilogue scales acc by 1/32 (B = 32*W).
// ---------------------------------------------------------------------------
__global__ __launch_bounds__(128, 4) void qkv_gemm(
    const float* __restrict__ bq, const float* __restrict__ bk,
    const float* __restrict__ bv, const float* __restrict__ emo)
{
    extern __shared__ char sm[];
    const int z = blockIdx.z;
    const unsigned short* W = (z == 0) ? g_wq16 : (z == 1) ? g_wk16 : g_wv16;
    const float* bias = (z == 0) ? bq : (z == 1) ? bk : bv;

    const int m0 = blockIdx.y * 64, n0 = blockIdx.x * 128;
    float acc[4][4][4];
    gemm_f16_core(g_xh, g_xl, W, sm, blockIdx.y, blockIdx.x, acc);

    const int tid = threadIdx.x, wn = tid >> 5, lane = tid & 31;
    const int g = lane >> 2, tg = lane & 3;
    const float sc = 0.03125f;

    if (z == 0) {
        #pragma unroll
        for (int mt = 0; mt < 4; mt++) {
            #pragma unroll
            for (int nt = 0; nt < 4; nt++) {
                const int n = n0 + wn * 32 + nt * 8 + 2 * tg;
                const int h = n >> 6, dh = n & 63;
                float b0 = bias[n]     + emo[n];
                float b1 = bias[n + 1] + emo[n + 1];
                #pragma unroll
                for (int half = 0; half < 2; half++) {
                    const int r = m0 + mt * 16 + g + half * 8;
                    const int bb = r >> 11, s = r & (NS - 1);
                    float2 v = make_float2(acc[mt][nt][2 * half] * sc + b0,
                                           acc[mt][nt][2 * half + 1] * sc + b1);
                    *(float2*)&g_q[(((size_t)bb * NH + h) * NS + s) * NDH + dh] = v;
                }
            }
        }
    } else if (z == 1) {
        // K -> B-frag tiles [bh][kt][...]: row = s&63, col = dh
        #pragma unroll
        for (int mt = 0; mt < 4; mt++) {
            #pragma unroll
            for (int nt = 0; nt < 4; nt++) {
                const int n = n0 + wn * 32 + nt * 8 + 2 * tg;
                const int h = n >> 6, dh = n & 63;
                float b0 = bias[n], b1 = bias[n + 1];
                #pragma unroll
                for (int half = 0; half < 2; half++) {
                    const int r = m0 + mt * 16 + g + half * 8;
                    const int bb = r >> 11, s = r & (NS - 1);
                    const int bh = bb * NH + h, kt = s >> 6;
                    uint32_t v = pack_h2(acc[mt][nt][2 * half] * sc + b0,
                                         acc[mt][nt][2 * half + 1] * sc + b1);
                    ((uint32_t*)g_kt16)[((size_t)(bh * 32 + kt)) * 2048
                                        + bfrag64_off(s & 63, dh)] = v;
                }
            }
        }
    } else {
        // V^T -> B-frag tiles: row = dh, col = s&63 (via smem transpose)
        unsigned short* vt = (unsigned short*)sm;   // [nl 0..127][sl 0..63], stride 72
        #pragma unroll
        for (int mt = 0; mt < 4; mt++) {
            #pragma unroll
            for (int nt = 0; nt < 4; nt++) {
                const int nl = wn * 32 + nt * 8 + 2 * tg;
                float b0 = bias[n0 + nl], b1 = bias[n0 + nl + 1];
                #pragma unroll
                for (int half = 0; half < 2; half++) {
                    const int sl = mt * 16 + g + half * 8;
                    vt[nl * 72 + sl]       = __half_as_ushort(
                        __float2half_rn(acc[mt][nt][2 * half] * sc + b0));
                    vt[(nl + 1) * 72 + sl] = __half_as_ushort(
                        __float2half_rn(acc[mt][nt][2 * half + 1] * sc + b1));
                }
            }
        }
        __syncthreads();
        const int bb = m0 >> 11, sbase = m0 & (NS - 1);
        const int kt = sbase >> 6;
        for (int i = tid; i < 128 * 32; i += 128) {
            const int nl = i >> 5, s2 = (i & 31) * 2;
            const int n = n0 + nl, h = n >> 6, dh = n & 63;
            const int bh = bb * NH + h;
            ((uint32_t*)g_vt16)[((size_t)(bh * 32 + kt)) * 2048
                                + bfrag64_off(dh, s2)] =
                *(const uint32_t*)&vt[nl * 72 + s2];
        }
    }
}

// ---------------------------------------------------------------------------
// Output projection (128 threads): (g_aoh+g_aol) @ g_wo16 -> out = acc/32 + bo
// ---------------------------------------------------------------------------
__global__ __launch_bounds__(128, 4) void out_gemm(
    const float* __restrict__ bo, float* __restrict__ out)
{
    extern __shared__ char sm[];
    const int m0 = blockIdx.y * 64, n0 = blockIdx.x * 128;
    float acc[4][4][4];
    gemm_f16_core(g_aoh, g_aol, g_wo16, sm, blockIdx.y, blockIdx.x, acc);

    const int tid = threadIdx.x, wn = tid >> 5, lane = tid & 31;
    const int g = lane >> 2, tg = lane & 3;
    const float sc = 0.03125f;

    #pragma unroll
    for (int mt = 0; mt < 4; mt++) {
        #pragma unroll
        for (int nt = 0; nt < 4; nt++) {
            const int n = n0 + wn * 32 + nt * 8 + 2 * tg;
            float b0 = bo[n], b1 = bo[n + 1];
            #pragma unroll
            for (int half = 0; half < 2; half++) {
                const int r = m0 + mt * 16 + g + half * 8;
                float2 v = make_float2(acc[mt][nt][2 * half] * sc + b0,
                                       acc[mt][nt][2 * half + 1] * sc + b1);
                *(float2*)&out[(size_t)r * ND + n] = v;
            }
        }
    }
}

// ---------------------------------------------------------------------------
// Flash attention, 128 threads / 64 q-rows / 4 CTAs per SM.
// K and V^T arrive in B-frag tile layout: every fragment = one LDS.64.
// Stage = K tile 8KB + V tile 8KB; 3-stage cp.async, 1 barrier per k-tile.
// ---------------------------------------------------------------------------
#define ATT_STAGE 16384
#define ATT_SMEM  (3 * ATT_STAGE)   // 49152

__global__ __launch_bounds__(128, 4) void attn_kernel(const int* __restrict__ mask)
{
    extern __shared__ char att_sm[];
    __shared__ float mb[3][64];

    const int bh = blockIdx.y;
    const int b  = bh >> 4;
    const int h  = bh & 15;
    const int q0 = blockIdx.x * 64;
    const float* Qp = g_q + (size_t)bh * NS * NDH;
    const unsigned short* KT = g_kt16 + (size_t)bh * 32 * 4096;
    const unsigned short* VT = g_vt16 + (size_t)bh * 32 * 4096;
    const int* mrow = mask + b * NS;

    const int tid = threadIdx.x, wid = tid >> 5, lane = tid & 31;
    const int g = lane >> 2, tg = lane & 3;
    const uint32_t sb = smem_u32(att_sm);

    auto issue = [&](int kb, int bf) {
        const uint32_t st = sb + bf * ATT_STAGE;
        const unsigned short* kp = KT + (size_t)kb * 4096;
        const unsigned short* vp = VT + (size_t)kb * 4096;
        #pragma unroll
        for (int i = 0; i < 4; i++) {
            const int f = tid + i * 128;
            CP16(st +        f * 16, kp + f * 8);
            CP16(st + 8192 + f * 16, vp + f * 8);
        }
        CP_COMMIT();
    };

    const float qs = 0.125f * LOG2E;
    uint32_t qh[4][4];
    {
        const float* q0p = Qp + (size_t)(q0 + wid * 16 + g) * NDH;
        const float* q1p = q0p + 8 * NDH;
        #pragma unroll
        for (int kk = 0; kk < 4; kk++) {
            float2 x;
            x = *(const float2*)(q0p + kk * 16 + 2 * tg);
            qh[kk][0] = pack_h2(qs * x.x, qs * x.y);
            x = *(const float2*)(q1p + kk * 16 + 2 * tg);
            qh[kk][1] = pack_h2(qs * x.x, qs * x.y);
            x = *(const float2*)(q0p + kk * 16 + 2 * tg + 8);
            qh[kk][2] = pack_h2(qs * x.x, qs * x.y);
            x = *(const float2*)(q1p + kk * 16 + 2 * tg + 8);
            qh[kk][3] = pack_h2(qs * x.x, qs * x.y);
        }
    }

    float o[8][4];
    #pragma unroll
    for (int nt = 0; nt < 8; nt++)
        #pragma unroll
        for (int i = 0; i < 4; i++) o[nt][i] = 0.f;
    float mrun[2] = {-1e30f, -1e30f}, lrun[2] = {0.f, 0.f};

    issue(0, 0);
    issue(1, 1);
    if (tid < 64) {
        mb[0][tid] = mrow[tid]      ? 0.f : -1e30f;
        mb[1][tid] = mrow[64 + tid] ? 0.f : -1e30f;
    }

    for (int kb = 0; kb < NS / 64; kb++) {
        const int bf = kb % 3;
        if (kb == NS / 64 - 1) CP_WAIT0(); else CP_WAIT1();
        __syncthreads();
        if (kb + 2 < NS / 64) {
            issue(kb + 2, (kb + 2) % 3);
            if (tid < 64)
                mb[(kb + 2) % 3][tid] = mrow[(kb + 2) * 64 + tid] ? 0.f : -1e30f;
        }

        const uint2* Kf = (const uint2*)(att_sm + bf * ATT_STAGE);
        const uint2* Vf = (const uint2*)(att_sm + bf * ATT_STAGE + 8192);

        // ---- S (log2 domain) = Q K^T : 1 LDS.64 + 1 mma per fragment ----
        float sc[8][4];
        #pragma unroll
        for (int nt = 0; nt < 8; nt++)
            #pragma unroll
            for (int i = 0; i < 4; i++) sc[nt][i] = 0.f;

        #pragma unroll
        for (int kk = 0; kk < 4; kk++) {
            #pragma unroll
            for (int nt = 0; nt < 8; nt++) {
                uint2 t = Kf[(kk * 8 + nt) * 32 + lane];
                uint32_t kb2[2] = { t.x, t.y };
                mma_fp16(sc[nt], qh[kk], kb2);
            }
        }

        // ---- mask bias ----
        #pragma unroll
        for (int nt = 0; nt < 8; nt++) {
            float2 mv = *(const float2*)&mb[bf][nt * 8 + 2 * tg];
            sc[nt][0] += mv.x; sc[nt][1] += mv.y;
            sc[nt][2] += mv.x; sc[nt][3] += mv.y;
        }

        // ---- online softmax, log2 domain (rows g, g+8; quad shfl) ----
        #pragma unroll
        for (int r = 0; r < 2; r++) {
            float mx = -1e30f;
            #pragma unroll
            for (int nt = 0; nt < 8; nt++)
                mx = fmaxf(mx, fmaxf(sc[nt][2 * r], sc[nt][2 * r + 1]));
            mx = fmaxf(mx, __shfl_xor_sync(0xffffffffu, mx, 1));
            mx = fmaxf(mx, __shfl_xor_sync(0xffffffffu, mx, 2));
            const float mn = fmaxf(mrun[r], mx);
            float sum = 0.f;
            #pragma unroll
            for (int nt = 0; nt < 8; nt++) {
                float p0 = ex2f(sc[nt][2 * r]     - mn);
                float p1 = ex2f(sc[nt][2 * r + 1] - mn);
                sc[nt][2 * r] = p0; sc[nt][2 * r + 1] = p1;
                sum += p0 + p1;
            }
            sum += __shfl_xor_sync(0xffffffffu, sum, 1);
            sum += __shfl_xor_sync(0xffffffffu, sum, 2);
            const float al = ex2f(mrun[r] - mn);
            lrun[r] = lrun[r] * al + sum;
            mrun[r] = mn;
            #pragma unroll
            for (int nt = 0; nt < 8; nt++) {
                o[nt][2 * r]     *= al;
                o[nt][2 * r + 1] *= al;
            }
        }

        // ---- O += P V : 1 LDS.64 + 1 mma per fragment ----
        #pragma unroll
        for (int kk = 0; kk < 4; kk++) {
            uint32_t ph[4];
            ph[0] = pack_h2(sc[2 * kk][0],     sc[2 * kk][1]);
            ph[1] = pack_h2(sc[2 * kk][2],     sc[2 * kk][3]);
            ph[2] = pack_h2(sc[2 * kk + 1][0], sc[2 * kk + 1][1]);
            ph[3] = pack_h2(sc[2 * kk + 1][2], sc[2 * kk + 1][3]);
            #pragma unroll
            for (int nt = 0; nt < 8; nt++) {
                uint2 t = Vf[(kk * 8 + nt) * 32 + lane];
                uint32_t v2[2] = { t.x, t.y };
                mma_fp16(o[nt], ph, v2);
            }
        }
    }

    // ---- normalize + split fp16 hi/lo + write 64-row A-frag layout ----
    const float inv0 = 1.0f / lrun[0];
    const float inv1 = 1.0f / lrun[1];
    const int m_lo = b * NS + q0 + wid * 16 + g;
    const int m_hi = m_lo + 8;
    uint32_t* aoh32 = (uint32_t*)g_aoh;
    uint32_t* aol32 = (uint32_t*)g_aol;
    #pragma unroll
    for (int nt = 0; nt < 8; nt++) {
        const int col = h * 64 + nt * 8 + 2 * tg;
        uint32_t hi, lo;
        split2h(o[nt][0] * inv0, o[nt][1] * inv0, hi, lo);
        size_t off = af16_off(m_lo, col);
        aoh32[off] = hi; aol32[off] = lo;
        split2h(o[nt][2] * inv1, o[nt][3] * inv1, hi, lo);
        off = af16_off(m_hi, col);
        aoh32[off] = hi; aol32[off] = lo;
    }
}

// ---------------------------------------------------------------------------
extern "C" void kernel_launch(void* const* d_in, const int* in_sizes, int n_in,
                              void* d_out, int out_size)
{
    const float* hs  = (const float*)d_in[0];
    const int*   msk = (const int*)  d_in[1];
    const float* Wq  = (const float*)d_in[2];
    const float* bq  = (const float*)d_in[3];
    const float* Wk  = (const float*)d_in[4];
    const float* bk  = (const float*)d_in[5];
    const float* Wv  = (const float*)d_in[6];
    const float* bv  = (const float*)d_in[7];
    const float* emo = (const float*)d_in[8];
    const float* Wo  = (const float*)d_in[9];
    const float* bo  = (const float*)d_in[10];
    float* out = (float*)d_out;

    cudaFuncSetAttribute(qkv_gemm, cudaFuncAttributeMaxDynamicSharedMemorySize, GEMM_SMEM);
    cudaFuncSetAttribute(out_gemm, cudaFuncAttributeMaxDynamicSharedMemorySize, GEMM_SMEM);
    cudaFuncSetAttribute(attn_kernel, cudaFuncAttributeMaxDynamicSharedMemorySize, ATT_SMEM);

    dim3 gr(128, 5);
    round_prep<<<gr, 256>>>(hs, Wq, Wk, Wv, Wo);

    dim3 gqkv(ND / 128, MT / 64, 3);
    qkv_gemm<<<gqkv, 128, GEMM_SMEM>>>(bq, bk, bv, emo);

    dim3 gatt(NS / 64, NB * NH);
    attn_kernel<<<gatt, 128, ATT_SMEM>>>(msk);

    dim3 gout(ND / 128, MT / 64);
    out_gemm<<<gout, 128, GEMM_SMEM>>>(bo, out);
}

// round 16
// speedup vs baseline: 1.4908x; 1.2991x over previous
#include <cuda_runtime.h>
#include <cuda_bf16.h>
#include <cuda_fp16.h>
#include <cstdint>
#include <math.h>

#define NB 2
#define NS 2048
#define ND 1024
#define NH 16
#define NDH 64
#define MT (NB*NS)          // 4096 rows in all GEMMs
#define LOG2E 1.4426950408889634f

// Scratch (allocation-free rule: __device__ globals)
__device__ float g_q [NB*NH*NS*NDH];   // [B,H,S,DH] fp32 (row-major)
// GEMM operands, fp16 fragment layouts:
//   A-layout: 64-row tiles [mb64][kb][2048 halves], B-layout [nb][kb][4096 halves]
__device__ unsigned short g_xh [MT*ND];   // X (single fp16, A-frag)
__device__ unsigned short g_wq16[ND*ND];  // 32*W in fp16, B-frag layout
__device__ unsigned short g_wk16[ND*ND];
__device__ unsigned short g_wv16[ND*ND];
__device__ unsigned short g_wo16[ND*ND];
__device__ unsigned short g_aoh[MT*ND];   // attention out (single fp16, A-frag)
// K tiles in B-frag layout: [bh][kt][4096 halves] (64 kpos x 64 d per tile)
// V^T tiles in B-frag layout: [bh][kt][4096 halves] (64 d x 64 kpos per tile)
__device__ unsigned short g_kt16 [NB*NH*NS*NDH];
__device__ unsigned short g_vt16 [NB*NH*NS*NDH];

// ===========================================================================
// Helpers
// ===========================================================================
__device__ __forceinline__ uint32_t smem_u32(const void* p) {
    uint32_t a;
    asm("{ .reg .u64 t; cvta.to.shared.u64 t, %1; cvt.u32.u64 %0, t; }"
        : "=r"(a) : "l"(p));
    return a;
}

__device__ __forceinline__ float ex2f(float x) {      // bare MUFU.EX2, ftz
    float y;
    asm("ex2.approx.ftz.f32 %0, %1;" : "=f"(y) : "f"(x));
    return y;
}

__device__ __forceinline__ void mma_fp16(float (&c)[4],
                                         const uint32_t (&a)[4],
                                         const uint32_t (&b)[2]) {
    asm volatile(
        "mma.sync.aligned.m16n8k16.row.col.f32.f16.f16.f32 "
        "{%0,%1,%2,%3}, {%4,%5,%6,%7}, {%8,%9}, {%0,%1,%2,%3};"
        : "+f"(c[0]), "+f"(c[1]), "+f"(c[2]), "+f"(c[3])
        : "r"(a[0]), "r"(a[1]), "r"(a[2]), "r"(a[3]), "r"(b[0]), "r"(b[1]));
}

__device__ __forceinline__ uint32_t pack_h2(float x0, float x1) {
    __half2 h = __floats2half2_rn(x0, x1);
    return *(uint32_t*)&h;
}

#define CP16(dst, src) \
    asm volatile("cp.async.cg.shared.global [%0], [%1], 16;" \
                 :: "r"(dst), "l"(src))
#define CP_COMMIT() asm volatile("cp.async.commit_group;" ::: "memory")
#define CP_WAIT1()  asm volatile("cp.async.wait_group 1;" ::: "memory")
#define CP_WAIT0()  asm volatile("cp.async.wait_group 0;" ::: "memory")

// A-fragment (64-row tiles) u32 index for element pair (m, k even)
__device__ __forceinline__ size_t af16_off(int m, int k) {
    const int mb = m >> 6, kb = k >> 5, c = (k >> 4) & 1;
    const int mf = (m >> 4) & 3, g = m & 7, mhalf = (m >> 3) & 1;
    const int tg = (k >> 1) & 3, khalf8 = (k >> 3) & 1;
    return ((size_t)(mb * 32 + kb)) * 1024
         + (size_t)((((c * 4 + mf) * 32 + g * 4 + tg) * 4) + khalf8 * 2 + mhalf);
}

// B-fragment 64x64 tile u32 index for element pair (row, col even)
__device__ __forceinline__ int bfrag64_off(int row, int col) {
    const int nt = row >> 3, g = row & 7;
    const int kk = col >> 4, khalf = (col >> 3) & 1, tg = (col >> 1) & 3;
    return (((kk * 8 + nt) * 32 + g * 4 + tg) * 2) + khalf;
}

#define STAGE_B   12288            // A 4K + B 8K
#define GEMM_SMEM (3 * STAGE_B)    // 36864, 3-stage

// ---------------------------------------------------------------------------
// fp16 single-term GEMM core, 128 threads (4 warps), CTA tile 64m x 128n.
// Warp w owns 64m x 32n. 3-stage, one barrier per k-tile.
// C = A * B, fp32 accum; caller scales by 1/32 (B = 32*W).
// ---------------------------------------------------------------------------
__device__ __forceinline__ void gemm_f16_core(
    const unsigned short* __restrict__ Ah,
    const unsigned short* __restrict__ Bf,
    char* sm, int mblk, int nblk, float (&acc)[4][4][4])
{
    const int tid  = threadIdx.x;
    const int wn   = tid >> 5, lane = tid & 31;

    #pragma unroll
    for (int mt = 0; mt < 4; mt++)
        #pragma unroll
        for (int nt = 0; nt < 4; nt++)
            #pragma unroll
            for (int i = 0; i < 4; i++) acc[mt][nt][i] = 0.f;

    const uint32_t sm_u = smem_u32(sm);

    auto issue_tile = [&](int kt, int bf) {
        const unsigned short* sA = Ah + ((size_t)(mblk * 32 + kt)) * 2048;
        const unsigned short* sB = Bf + ((size_t)(nblk * 32 + kt)) * 4096;
        const uint32_t st = sm_u + bf * STAGE_B;
        #pragma unroll
        for (int i = 0; i < 2; i++) {
            const int f = tid + i * 128;
            CP16(st + f * 16, sA + f * 8);
        }
        #pragma unroll
        for (int i = 0; i < 4; i++) {
            const int f = tid + i * 128;
            CP16(st + 4096 + f * 16, sB + f * 8);
        }
        CP_COMMIT();
    };

    issue_tile(0, 0);
    issue_tile(1, 1);

    for (int kt = 0; kt < 32; kt++) {
        const int bf = kt % 3;
        if (kt == 31) CP_WAIT0(); else CP_WAIT1();
        __syncthreads();
        if (kt + 2 < 32) issue_tile(kt + 2, (kt + 2) % 3);

        const uint4* A4 = (const uint4*)(sm + bf * STAGE_B);
        const uint2* B2 = (const uint2*)(sm + bf * STAGE_B + 4096);

        #pragma unroll
        for (int c = 0; c < 2; c++) {
            uint2 bv[4];
            #pragma unroll
            for (int nt = 0; nt < 4; nt++)
                bv[nt] = B2[(c * 16 + wn * 4 + nt) * 32 + lane];

            uint32_t a[4][4];
            #pragma unroll
            for (int mt = 0; mt < 4; mt++) {
                uint4 t = A4[(c * 4 + mt) * 32 + lane];
                a[mt][0] = t.x; a[mt][1] = t.y; a[mt][2] = t.z; a[mt][3] = t.w;
            }
            #pragma unroll
            for (int mt = 0; mt < 4; mt++)
                #pragma unroll
                for (int nt = 0; nt < 4; nt++) {
                    uint32_t b2[2] = { bv[nt].x, bv[nt].y };
                    mma_fp16(acc[mt][nt], a[mt], b2);
                }
        }
    }
    __syncthreads();   // protect smem reuse by epilogue
}

// ---------------------------------------------------------------------------
// Round prep: X -> single fp16 (64-row A-frag tiles); W -> fp16 of 32*W (B-frag).
// ---------------------------------------------------------------------------
__global__ __launch_bounds__(256) void round_prep(
    const float* __restrict__ X,  const float* __restrict__ Wq,
    const float* __restrict__ Wk, const float* __restrict__ Wv,
    const float* __restrict__ Wo)
{
    const int z = blockIdx.y;
    if (z == 0) {
        for (int t = blockIdx.x * 256 + threadIdx.x; t < MT * ND / 2;
             t += gridDim.x * 256) {
            const int tile = t >> 10, w = t & 1023;
            const int j = w & 3, lane = (w >> 2) & 31, grp = w >> 7;
            const int c = grp >> 2, mf = grp & 3;
            const int mb = tile >> 5, kb = tile & 31;
            const int g = lane >> 2, tg = lane & 3;
            const int m = mb * 64 + mf * 16 + (j & 1) * 8 + g;
            const int k = kb * 32 + c * 16 + (j >> 1) * 8 + 2 * tg;
            ((uint32_t*)g_xh)[t] = pack_h2(X[(size_t)m * ND + k],
                                           X[(size_t)m * ND + k + 1]);
        }
    } else {
        const float* s = (z == 1) ? Wq : (z == 2) ? Wk : (z == 3) ? Wv : Wo;
        unsigned short* d = (z == 1) ? g_wq16 : (z == 2) ? g_wk16
                          : (z == 3) ? g_wv16 : g_wo16;
        for (int t = blockIdx.x * 256 + threadIdx.x; t < ND * ND / 2;
             t += gridDim.x * 256) {
            const int tile = t >> 11, w = t & 2047;
            const int jj = w & 1, lane = (w >> 1) & 31;
            const int nf = (w >> 6) & 15, c = (w >> 10) & 1;
            const int nb = tile >> 5, kb = tile & 31;
            const int g = lane >> 2, tg = lane & 3;
            const int k = kb * 32 + c * 16 + jj * 8 + 2 * tg;
            const int n = nb * 128 + nf * 8 + g;
            ((uint32_t*)d)[t] = pack_h2(32.f * s[(size_t)k * ND + n],
                                        32.f * s[(size_t)(k + 1) * ND + n]);
        }
    }
}

// ---------------------------------------------------------------------------
// QKV projection (128 threads, 64x128 tile): z=0 -> Q fp32 (+bias+emotion);
// z=1 -> K fp16 B-frag tiles; z=2 -> V^T fp16 B-frag tiles (via smem).
// Epilogue scales acc by 1/32 (B = 32*W).
// ---------------------------------------------------------------------------
__global__ __launch_bounds__(128, 4) void qkv_gemm(
    const float* __restrict__ bq, const float* __restrict__ bk,
    const float* __restrict__ bv, const float* __restrict__ emo)
{
    extern __shared__ char sm[];
    const int z = blockIdx.z;
    const unsigned short* W = (z == 0) ? g_wq16 : (z == 1) ? g_wk16 : g_wv16;
    const float* bias = (z == 0) ? bq : (z == 1) ? bk : bv;

    const int m0 = blockIdx.y * 64, n0 = blockIdx.x * 128;
    float acc[4][4][4];
    gemm_f16_core(g_xh, W, sm, blockIdx.y, blockIdx.x, acc);

    const int tid = threadIdx.x, wn = tid >> 5, lane = tid & 31;
    const int g = lane >> 2, tg = lane & 3;
    const float sc = 0.03125f;

    if (z == 0) {
        #pragma unroll
        for (int mt = 0; mt < 4; mt++) {
            #pragma unroll
            for (int nt = 0; nt < 4; nt++) {
                const int n = n0 + wn * 32 + nt * 8 + 2 * tg;
                const int h = n >> 6, dh = n & 63;
                float b0 = bias[n]     + emo[n];
                float b1 = bias[n + 1] + emo[n + 1];
                #pragma unroll
                for (int half = 0; half < 2; half++) {
                    const int r = m0 + mt * 16 + g + half * 8;
                    const int bb = r >> 11, s = r & (NS - 1);
                    float2 v = make_float2(acc[mt][nt][2 * half] * sc + b0,
                                           acc[mt][nt][2 * half + 1] * sc + b1);
                    *(float2*)&g_q[(((size_t)bb * NH + h) * NS + s) * NDH + dh] = v;
                }
            }
        }
    } else if (z == 1) {
        // K -> B-frag tiles [bh][kt][...]: row = s&63, col = dh
        #pragma unroll
        for (int mt = 0; mt < 4; mt++) {
            #pragma unroll
            for (int nt = 0; nt < 4; nt++) {
                const int n = n0 + wn * 32 + nt * 8 + 2 * tg;
                const int h = n >> 6, dh = n & 63;
                float b0 = bias[n], b1 = bias[n + 1];
                #pragma unroll
                for (int half = 0; half < 2; half++) {
                    const int r = m0 + mt * 16 + g + half * 8;
                    const int bb = r >> 11, s = r & (NS - 1);
                    const int bh = bb * NH + h, kt = s >> 6;
                    uint32_t v = pack_h2(acc[mt][nt][2 * half] * sc + b0,
                                         acc[mt][nt][2 * half + 1] * sc + b1);
                    ((uint32_t*)g_kt16)[((size_t)(bh * 32 + kt)) * 2048
                                        + bfrag64_off(s & 63, dh)] = v;
                }
            }
        }
    } else {
        // V^T -> B-frag tiles: row = dh, col = s&63 (via smem transpose)
        unsigned short* vt = (unsigned short*)sm;   // [nl 0..127][sl 0..63], stride 72
        #pragma unroll
        for (int mt = 0; mt < 4; mt++) {
            #pragma unroll
            for (int nt = 0; nt < 4; nt++) {
                const int nl = wn * 32 + nt * 8 + 2 * tg;
                float b0 = bias[n0 + nl], b1 = bias[n0 + nl + 1];
                #pragma unroll
                for (int half = 0; half < 2; half++) {
                    const int sl = mt * 16 + g + half * 8;
                    vt[nl * 72 + sl]       = __half_as_ushort(
                        __float2half_rn(acc[mt][nt][2 * half] * sc + b0));
                    vt[(nl + 1) * 72 + sl] = __half_as_ushort(
                        __float2half_rn(acc[mt][nt][2 * half + 1] * sc + b1));
                }
            }
        }
        __syncthreads();
        const int bb = m0 >> 11, sbase = m0 & (NS - 1);
        const int kt = sbase >> 6;
        for (int i = tid; i < 128 * 32; i += 128) {
            const int nl = i >> 5, s2 = (i & 31) * 2;
            const int n = n0 + nl, h = n >> 6, dh = n & 63;
            const int bh = bb * NH + h;
            ((uint32_t*)g_vt16)[((size_t)(bh * 32 + kt)) * 2048
                                + bfrag64_off(dh, s2)] =
                *(const uint32_t*)&vt[nl * 72 + s2];
        }
    }
}

// ---------------------------------------------------------------------------
// Output projection (128 threads): g_aoh @ g_wo16 -> out = acc/32 + bo
// ---------------------------------------------------------------------------
__global__ __launch_bounds__(128, 4) void out_gemm(
    const float* __restrict__ bo, float* __restrict__ out)
{
    extern __shared__ char sm[];
    const int m0 = blockIdx.y * 64, n0 = blockIdx.x * 128;
    float acc[4][4][4];
    gemm_f16_core(g_aoh, g_wo16, sm, blockIdx.y, blockIdx.x, acc);

    const int tid = threadIdx.x, wn = tid >> 5, lane = tid & 31;
    const int g = lane >> 2, tg = lane & 3;
    const float sc = 0.03125f;

    #pragma unroll
    for (int mt = 0; mt < 4; mt++) {
        #pragma unroll
        for (int nt = 0; nt < 4; nt++) {
            const int n = n0 + wn * 32 + nt * 8 + 2 * tg;
            float b0 = bo[n], b1 = bo[n + 1];
            #pragma unroll
            for (int half = 0; half < 2; half++) {
                const int r = m0 + mt * 16 + g + half * 8;
                float2 v = make_float2(acc[mt][nt][2 * half] * sc + b0,
                                       acc[mt][nt][2 * half + 1] * sc + b1);
                *(float2*)&out[(size_t)r * ND + n] = v;
            }
        }
    }
}

// ---------------------------------------------------------------------------
// Flash attention, 128 threads / 64 q-rows / 4 CTAs per SM.
// K and V^T arrive in B-frag tile layout: every fragment = one LDS.64.
// Stage = K tile 8KB + V tile 8KB; 3-stage cp.async, 1 barrier per k-tile.
// ---------------------------------------------------------------------------
#define ATT_STAGE 16384
#define ATT_SMEM  (3 * ATT_STAGE)   // 49152

__global__ __launch_bounds__(128, 4) void attn_kernel(const int* __restrict__ mask)
{
    extern __shared__ char att_sm[];
    __shared__ float mb[3][64];

    const int bh = blockIdx.y;
    const int b  = bh >> 4;
    const int h  = bh & 15;
    const int q0 = blockIdx.x * 64;
    const float* Qp = g_q + (size_t)bh * NS * NDH;
    const unsigned short* KT = g_kt16 + (size_t)bh * 32 * 4096;
    const unsigned short* VT = g_vt16 + (size_t)bh * 32 * 4096;
    const int* mrow = mask + b * NS;

    const int tid = threadIdx.x, wid = tid >> 5, lane = tid & 31;
    const int g = lane >> 2, tg = lane & 3;
    const uint32_t sb = smem_u32(att_sm);

    auto issue = [&](int kb, int bf) {
        const uint32_t st = sb + bf * ATT_STAGE;
        const unsigned short* kp = KT + (size_t)kb * 4096;
        const unsigned short* vp = VT + (size_t)kb * 4096;
        #pragma unroll
        for (int i = 0; i < 4; i++) {
            const int f = tid + i * 128;
            CP16(st +        f * 16, kp + f * 8);
            CP16(st + 8192 + f * 16, vp + f * 8);
        }
        CP_COMMIT();
    };

    const float qs = 0.125f * LOG2E;
    uint32_t qh[4][4];
    {
        const float* q0p = Qp + (size_t)(q0 + wid * 16 + g) * NDH;
        const float* q1p = q0p + 8 * NDH;
        #pragma unroll
        for (int kk = 0; kk < 4; kk++) {
            float2 x;
            x = *(const float2*)(q0p + kk * 16 + 2 * tg);
            qh[kk][0] = pack_h2(qs * x.x, qs * x.y);
            x = *(const float2*)(q1p + kk * 16 + 2 * tg);
            qh[kk][1] = pack_h2(qs * x.x, qs * x.y);
            x = *(const float2*)(q0p + kk * 16 + 2 * tg + 8);
            qh[kk][2] = pack_h2(qs * x.x, qs * x.y);
            x = *(const float2*)(q1p + kk * 16 + 2 * tg + 8);
            qh[kk][3] = pack_h2(qs * x.x, qs * x.y);
        }
    }

    float o[8][4];
    #pragma unroll
    for (int nt = 0; nt < 8; nt++)
        #pragma unroll
        for (int i = 0; i < 4; i++) o[nt][i] = 0.f;
    float mrun[2] = {-1e30f, -1e30f}, lrun[2] = {0.f, 0.f};

    issue(0, 0);
    issue(1, 1);
    if (tid < 64) {
        mb[0][tid] = mrow[tid]      ? 0.f : -1e30f;
        mb[1][tid] = mrow[64 + tid] ? 0.f : -1e30f;
    }

    for (int kb = 0; kb < NS / 64; kb++) {
        const int bf = kb % 3;
        if (kb == NS / 64 - 1) CP_WAIT0(); else CP_WAIT1();
        __syncthreads();
        if (kb + 2 < NS / 64) {
            issue(kb + 2, (kb + 2) % 3);
            if (tid < 64)
                mb[(kb + 2) % 3][tid] = mrow[(kb + 2) * 64 + tid] ? 0.f : -1e30f;
        }

        const uint2* Kf = (const uint2*)(att_sm + bf * ATT_STAGE);
        const uint2* Vf = (const uint2*)(att_sm + bf * ATT_STAGE + 8192);

        // ---- S (log2 domain) = Q K^T : 1 LDS.64 + 1 mma per fragment ----
        float sc[8][4];
        #pragma unroll
        for (int nt = 0; nt < 8; nt++)
            #pragma unroll
            for (int i = 0; i < 4; i++) sc[nt][i] = 0.f;

        #pragma unroll
        for (int kk = 0; kk < 4; kk++) {
            #pragma unroll
            for (int nt = 0; nt < 8; nt++) {
                uint2 t = Kf[(kk * 8 + nt) * 32 + lane];
                uint32_t kb2[2] = { t.x, t.y };
                mma_fp16(sc[nt], qh[kk], kb2);
            }
        }

        // ---- mask bias ----
        #pragma unroll
        for (int nt = 0; nt < 8; nt++) {
            float2 mv = *(const float2*)&mb[bf][nt * 8 + 2 * tg];
            sc[nt][0] += mv.x; sc[nt][1] += mv.y;
            sc[nt][2] += mv.x; sc[nt][3] += mv.y;
        }

        // ---- online softmax, log2 domain (rows g, g+8; quad shfl) ----
        #pragma unroll
        for (int r = 0; r < 2; r++) {
            float mx = -1e30f;
            #pragma unroll
            for (int nt = 0; nt < 8; nt++)
                mx = fmaxf(mx, fmaxf(sc[nt][2 * r], sc[nt][2 * r + 1]));
            mx = fmaxf(mx, __shfl_xor_sync(0xffffffffu, mx, 1));
            mx = fmaxf(mx, __shfl_xor_sync(0xffffffffu, mx, 2));
            const float mn = fmaxf(mrun[r], mx);
            float sum = 0.f;
            #pragma unroll
            for (int nt = 0; nt < 8; nt++) {
                float p0 = ex2f(sc[nt][2 * r]     - mn);
                float p1 = ex2f(sc[nt][2 * r + 1] - mn);
                sc[nt][2 * r] = p0; sc[nt][2 * r + 1] = p1;
                sum += p0 + p1;
            }
            sum += __shfl_xor_sync(0xffffffffu, sum, 1);
            sum += __shfl_xor_sync(0xffffffffu, sum, 2);
            const float al = ex2f(mrun[r] - mn);
            lrun[r] = lrun[r] * al + sum;
            mrun[r] = mn;
            #pragma unroll
            for (int nt = 0; nt < 8; nt++) {
                o[nt][2 * r]     *= al;
                o[nt][2 * r + 1] *= al;
            }
        }

        // ---- O += P V : 1 LDS.64 + 1 mma per fragment ----
        #pragma unroll
        for (int kk = 0; kk < 4; kk++) {
            uint32_t ph[4];
            ph[0] = pack_h2(sc[2 * kk][0],     sc[2 * kk][1]);
            ph[1] = pack_h2(sc[2 * kk][2],     sc[2 * kk][3]);
            ph[2] = pack_h2(sc[2 * kk + 1][0], sc[2 * kk + 1][1]);
            ph[3] = pack_h2(sc[2 * kk + 1][2], sc[2 * kk + 1][3]);
            #pragma unroll
            for (int nt = 0; nt < 8; nt++) {
                uint2 t = Vf[(kk * 8 + nt) * 32 + lane];
                uint32_t v2[2] = { t.x, t.y };
                mma_fp16(o[nt], ph, v2);
            }
        }
    }

    // ---- normalize + pack single fp16 + write 64-row A-frag layout ----
    const float inv0 = 1.0f / lrun[0];
    const float inv1 = 1.0f / lrun[1];
    const int m_lo = b * NS + q0 + wid * 16 + g;
    const int m_hi = m_lo + 8;
    uint32_t* aoh32 = (uint32_t*)g_aoh;
    #pragma unroll
    for (int nt = 0; nt < 8; nt++) {
        const int col = h * 64 + nt * 8 + 2 * tg;
        aoh32[af16_off(m_lo, col)] = pack_h2(o[nt][0] * inv0, o[nt][1] * inv0);
        aoh32[af16_off(m_hi, col)] = pack_h2(o[nt][2] * inv1, o[nt][3] * inv1);
    }
}

// ---------------------------------------------------------------------------
extern "C" void kernel_launch(void* const* d_in, const int* in_sizes, int n_in,
                              void* d_out, int out_size)
{
    const float* hs  = (const float*)d_in[0];
    const int*   msk = (const int*)  d_in[1];
    const float* Wq  = (const float*)d_in[2];
    const float* bq  = (const float*)d_in[3];
    const float* Wk  = (const float*)d_in[4];
    const float* bk  = (const float*)d_in[5];
    const float* Wv  = (const float*)d_in[6];
    const float* bv  = (const float*)d_in[7];
    const float* emo = (const float*)d_in[8];
    const float* Wo  = (const float*)d_in[9];
    const float* bo  = (const float*)d_in[10];
    float* out = (float*)d_out;

    cudaFuncSetAttribute(qkv_gemm, cudaFuncAttributeMaxDynamicSharedMemorySize, GEMM_SMEM);
    cudaFuncSetAttribute(out_gemm, cudaFuncAttributeMaxDynamicSharedMemorySize, GEMM_SMEM);
    cudaFuncSetAttribute(attn_kernel, cudaFuncAttributeMaxDynamicSharedMemorySize, ATT_SMEM);

    dim3 gr(128, 5);
    round_prep<<<gr, 256>>>(hs, Wq, Wk, Wv, Wo);

    dim3 gqkv(ND / 128, MT / 64, 3);
    qkv_gemm<<<gqkv, 128, GEMM_SMEM>>>(bq, bk, bv, emo);

    dim3 gatt(NS / 64, NB * NH);
    attn_kernel<<<gatt, 128, ATT_SMEM>>>(msk);

    dim3 gout(ND / 128, MT / 64);
    out_gemm<<<gout, 128, GEMM_SMEM>>>(bo, out);
}

// round 17
// speedup vs baseline: 1.4995x; 1.0059x over previous
#include <cuda_runtime.h>
#include <cuda_bf16.h>
#include <cuda_fp16.h>
#include <cstdint>
#include <math.h>

#define NB 2
#define NS 2048
#define ND 1024
#define NH 16
#define NDH 64
#define MT (NB*NS)          // 4096 rows in all GEMMs
#define LOG2E 1.4426950408889634f

// Scratch (allocation-free rule: __device__ globals)
__device__ float g_q [NB*NH*NS*NDH];   // [B,H,S,DH] fp32 (row-major)
// GEMM operands, fp16 fragment layouts (vectorized lane-major uint4 tiles):
//   A-layout: 64-row tiles [mb64][kb][2048 halves]
//   B-layout (weights): [nb][kb][4096 halves], uint4 idx = ((c*4+wn)*2+j)*32+lane
__device__ unsigned short g_xh [MT*ND];   // X (single fp16, A-frag)
__device__ unsigned short g_wq16[ND*ND];  // 32*W in fp16, vectorized B-frag
__device__ unsigned short g_wk16[ND*ND];
__device__ unsigned short g_wv16[ND*ND];
__device__ unsigned short g_wo16[ND*ND];
__device__ unsigned short g_aoh[MT*ND];   // attention out (single fp16, A-frag)
// K / V^T tiles, vectorized B-frag 64x64: uint4 idx = (kk*4+j)*32+lane
__device__ unsigned short g_kt16 [NB*NH*NS*NDH];
__device__ unsigned short g_vt16 [NB*NH*NS*NDH];

// ===========================================================================
// Helpers
// ===========================================================================
__device__ __forceinline__ uint32_t smem_u32(const void* p) {
    uint32_t a;
    asm("{ .reg .u64 t; cvta.to.shared.u64 t, %1; cvt.u32.u64 %0, t; }"
        : "=r"(a) : "l"(p));
    return a;
}

__device__ __forceinline__ float ex2f(float x) {      // bare MUFU.EX2, ftz
    float y;
    asm("ex2.approx.ftz.f32 %0, %1;" : "=f"(y) : "f"(x));
    return y;
}

__device__ __forceinline__ void mma_fp16(float (&c)[4],
                                         const uint32_t (&a)[4],
                                         const uint32_t (&b)[2]) {
    asm volatile(
        "mma.sync.aligned.m16n8k16.row.col.f32.f16.f16.f32 "
        "{%0,%1,%2,%3}, {%4,%5,%6,%7}, {%8,%9}, {%0,%1,%2,%3};"
        : "+f"(c[0]), "+f"(c[1]), "+f"(c[2]), "+f"(c[3])
        : "r"(a[0]), "r"(a[1]), "r"(a[2]), "r"(a[3]), "r"(b[0]), "r"(b[1]));
}

__device__ __forceinline__ uint32_t pack_h2(float x0, float x1) {
    __half2 h = __floats2half2_rn(x0, x1);
    return *(uint32_t*)&h;
}

#define CP16(dst, src) \
    asm volatile("cp.async.cg.shared.global [%0], [%1], 16;" \
                 :: "r"(dst), "l"(src))
#define CP_COMMIT() asm volatile("cp.async.commit_group;" ::: "memory")
#define CP_WAIT1()  asm volatile("cp.async.wait_group 1;" ::: "memory")
#define CP_WAIT0()  asm volatile("cp.async.wait_group 0;" ::: "memory")

// A-fragment (64-row tiles) u32 index for element pair (m, k even)
__device__ __forceinline__ size_t af16_off(int m, int k) {
    const int mb = m >> 6, kb = k >> 5, c = (k >> 4) & 1;
    const int mf = (m >> 4) & 3, g = m & 7, mhalf = (m >> 3) & 1;
    const int tg = (k >> 1) & 3, khalf8 = (k >> 3) & 1;
    return ((size_t)(mb * 32 + kb)) * 1024
         + (size_t)((((c * 4 + mf) * 32 + g * 4 + tg) * 4) + khalf8 * 2 + mhalf);
}

// Vectorized B-frag 64x64 tile u32 index for element pair (row, col even):
//   uint4 idx = (kk*4 + j)*32 + lane ; contains fragments nt=2j (x,y), 2j+1 (z,w)
__device__ __forceinline__ int bfragv_off(int row, int col) {
    const int nt = row >> 3, g = row & 7;
    const int kk = col >> 4, khalf = (col >> 3) & 1, tg = (col >> 1) & 3;
    const int j = nt >> 1, p = nt & 1, lane = g * 4 + tg;
    return ((((kk * 4 + j) * 32 + lane) * 2 + p) * 2) + khalf;
}

#define STAGE_B   12288            // A 4K + B 8K
#define GEMM_SMEM (3 * STAGE_B)    // 36864, 3-stage

// ---------------------------------------------------------------------------
// fp16 single-term GEMM core, 128 threads (4 warps), CTA tile 64m x 128n.
// B fragments: 2 LDS.128 per (c, warp). 3-stage, one barrier per k-tile.
// C = A * B, fp32 accum; caller scales by 1/32 (B = 32*W).
// ---------------------------------------------------------------------------
__device__ __forceinline__ void gemm_f16_core(
    const unsigned short* __restrict__ Ah,
    const unsigned short* __restrict__ Bf,
    char* sm, int mblk, int nblk, float (&acc)[4][4][4])
{
    const int tid  = threadIdx.x;
    const int wn   = tid >> 5, lane = tid & 31;

    #pragma unroll
    for (int mt = 0; mt < 4; mt++)
        #pragma unroll
        for (int nt = 0; nt < 4; nt++)
            #pragma unroll
            for (int i = 0; i < 4; i++) acc[mt][nt][i] = 0.f;

    const uint32_t sm_u = smem_u32(sm);

    auto issue_tile = [&](int kt, int bf) {
        const unsigned short* sA = Ah + ((size_t)(mblk * 32 + kt)) * 2048;
        const unsigned short* sB = Bf + ((size_t)(nblk * 32 + kt)) * 4096;
        const uint32_t st = sm_u + bf * STAGE_B;
        #pragma unroll
        for (int i = 0; i < 2; i++) {
            const int f = tid + i * 128;
            CP16(st + f * 16, sA + f * 8);
        }
        #pragma unroll
        for (int i = 0; i < 4; i++) {
            const int f = tid + i * 128;
            CP16(st + 4096 + f * 16, sB + f * 8);
        }
        CP_COMMIT();
    };

    issue_tile(0, 0);
    issue_tile(1, 1);

    for (int kt = 0; kt < 32; kt++) {
        const int bf = kt % 3;
        if (kt == 31) CP_WAIT0(); else CP_WAIT1();
        __syncthreads();
        if (kt + 2 < 32) issue_tile(kt + 2, (kt + 2) % 3);

        const uint4* A4 = (const uint4*)(sm + bf * STAGE_B);
        const uint4* B4 = (const uint4*)(sm + bf * STAGE_B + 4096);

        #pragma unroll
        for (int c = 0; c < 2; c++) {
            uint4 b01 = B4[((c * 4 + wn) * 2 + 0) * 32 + lane];
            uint4 b23 = B4[((c * 4 + wn) * 2 + 1) * 32 + lane];
            uint2 bv[4] = { {b01.x, b01.y}, {b01.z, b01.w},
                            {b23.x, b23.y}, {b23.z, b23.w} };

            uint32_t a[4][4];
            #pragma unroll
            for (int mt = 0; mt < 4; mt++) {
                uint4 t = A4[(c * 4 + mt) * 32 + lane];
                a[mt][0] = t.x; a[mt][1] = t.y; a[mt][2] = t.z; a[mt][3] = t.w;
            }
            #pragma unroll
            for (int mt = 0; mt < 4; mt++)
                #pragma unroll
                for (int nt = 0; nt < 4; nt++) {
                    uint32_t b2[2] = { bv[nt].x, bv[nt].y };
                    mma_fp16(acc[mt][nt], a[mt], b2);
                }
        }
    }
    __syncthreads();   // protect smem reuse by epilogue
}

// ---------------------------------------------------------------------------
// Round prep: X -> single fp16 (64-row A-frag); W -> fp16 of 32*W (vec B-frag).
// ---------------------------------------------------------------------------
__global__ __launch_bounds__(256) void round_prep(
    const float* __restrict__ X,  const float* __restrict__ Wq,
    const float* __restrict__ Wk, const float* __restrict__ Wv,
    const float* __restrict__ Wo)
{
    const int z = blockIdx.y;
    if (z == 0) {
        for (int t = blockIdx.x * 256 + threadIdx.x; t < MT * ND / 2;
             t += gridDim.x * 256) {
            const int tile = t >> 10, w = t & 1023;
            const int j = w & 3, lane = (w >> 2) & 31, grp = w >> 7;
            const int c = grp >> 2, mf = grp & 3;
            const int mb = tile >> 5, kb = tile & 31;
            const int g = lane >> 2, tg = lane & 3;
            const int m = mb * 64 + mf * 16 + (j & 1) * 8 + g;
            const int k = kb * 32 + c * 16 + (j >> 1) * 8 + 2 * tg;
            ((uint32_t*)g_xh)[t] = pack_h2(X[(size_t)m * ND + k],
                                           X[(size_t)m * ND + k + 1]);
        }
    } else {
        const float* s = (z == 1) ? Wq : (z == 2) ? Wk : (z == 3) ? Wv : Wo;
        unsigned short* d = (z == 1) ? g_wq16 : (z == 2) ? g_wk16
                          : (z == 3) ? g_wv16 : g_wo16;
        for (int t = blockIdx.x * 256 + threadIdx.x; t < ND * ND / 2;
             t += gridDim.x * 256) {
            const int tile = t >> 11, w = t & 2047;
            const int khalf = w & 1, u2 = w >> 1;
            const int p = u2 & 1, u4 = u2 >> 1;       // u4: 0..511
            const int lane = u4 & 31, j = (u4 >> 5) & 1;
            const int wn = (u4 >> 6) & 3, c = (u4 >> 8) & 1;
            const int nt = 2 * j + p, nf = wn * 4 + nt;
            const int nb = tile >> 5, kb = tile & 31;
            const int g = lane >> 2, tg = lane & 3;
            const int k = kb * 32 + c * 16 + khalf * 8 + 2 * tg;
            const int n = nb * 128 + nf * 8 + g;
            ((uint32_t*)d)[t] = pack_h2(32.f * s[(size_t)k * ND + n],
                                        32.f * s[(size_t)(k + 1) * ND + n]);
        }
    }
}

// ---------------------------------------------------------------------------
// QKV projection (128 threads, 64x128 tile): z=0 -> Q fp32 (+bias+emotion);
// z=1 -> K vec-B-frag tiles; z=2 -> V^T vec-B-frag tiles (via smem).
// Epilogue scales acc by 1/32 (B = 32*W).
// ---------------------------------------------------------------------------
__global__ __launch_bounds__(128, 4) void qkv_gemm(
    const float* __restrict__ bq, const float* __restrict__ bk,
    const float* __restrict__ bv, const float* __restrict__ emo)
{
    extern __shared__ char sm[];
    const int z = blockIdx.z;
    const unsigned short* W = (z == 0) ? g_wq16 : (z == 1) ? g_wk16 : g_wv16;
    const float* bias = (z == 0) ? bq : (z == 1) ? bk : bv;

    const int m0 = blockIdx.y * 64, n0 = blockIdx.x * 128;
    float acc[4][4][4];
    gemm_f16_core(g_xh, W, sm, blockIdx.y, blockIdx.x, acc);

    const int tid = threadIdx.x, wn = tid >> 5, lane = tid & 31;
    const int g = lane >> 2, tg = lane & 3;
    const float sc = 0.03125f;

    if (z == 0) {
        #pragma unroll
        for (int mt = 0; mt < 4; mt++) {
            #pragma unroll
            for (int nt = 0; nt < 4; nt++) {
                const int n = n0 + wn * 32 + nt * 8 + 2 * tg;
                const int h = n >> 6, dh = n & 63;
                float b0 = bias[n]     + emo[n];
                float b1 = bias[n + 1] + emo[n + 1];
                #pragma unroll
                for (int half = 0; half < 2; half++) {
                    const int r = m0 + mt * 16 + g + half * 8;
                    const int bb = r >> 11, s = r & (NS - 1);
                    float2 v = make_float2(acc[mt][nt][2 * half] * sc + b0,
                                           acc[mt][nt][2 * half + 1] * sc + b1);
                    *(float2*)&g_q[(((size_t)bb * NH + h) * NS + s) * NDH + dh] = v;
                }
            }
        }
    } else if (z == 1) {
        // K -> vec B-frag tiles [bh][kt][...]: row = s&63, col = dh
        #pragma unroll
        for (int mt = 0; mt < 4; mt++) {
            #pragma unroll
            for (int nt = 0; nt < 4; nt++) {
                const int n = n0 + wn * 32 + nt * 8 + 2 * tg;
                const int h = n >> 6, dh = n & 63;
                float b0 = bias[n], b1 = bias[n + 1];
                #pragma unroll
                for (int half = 0; half < 2; half++) {
                    const int r = m0 + mt * 16 + g + half * 8;
                    const int bb = r >> 11, s = r & (NS - 1);
                    const int bh = bb * NH + h, kt = s >> 6;
                    uint32_t v = pack_h2(acc[mt][nt][2 * half] * sc + b0,
                                         acc[mt][nt][2 * half + 1] * sc + b1);
                    ((uint32_t*)g_kt16)[((size_t)(bh * 32 + kt)) * 2048
                                        + bfragv_off(s & 63, dh)] = v;
                }
            }
        }
    } else {
        // V^T -> vec B-frag tiles: row = dh, col = s&63 (via smem transpose)
        unsigned short* vt = (unsigned short*)sm;   // [nl 0..127][sl 0..63], stride 72
        #pragma unroll
        for (int mt = 0; mt < 4; mt++) {
            #pragma unroll
            for (int nt = 0; nt < 4; nt++) {
                const int nl = wn * 32 + nt * 8 + 2 * tg;
                float b0 = bias[n0 + nl], b1 = bias[n0 + nl + 1];
                #pragma unroll
                for (int half = 0; half < 2; half++) {
                    const int sl = mt * 16 + g + half * 8;
                    vt[nl * 72 + sl]       = __half_as_ushort(
                        __float2half_rn(acc[mt][nt][2 * half] * sc + b0));
                    vt[(nl + 1) * 72 + sl] = __half_as_ushort(
                        __float2half_rn(acc[mt][nt][2 * half + 1] * sc + b1));
                }
            }
        }
        __syncthreads();
        const int bb = m0 >> 11, sbase = m0 & (NS - 1);
        const int kt = sbase >> 6;
        for (int i = tid; i < 128 * 32; i += 128) {
            const int nl = i >> 5, s2 = (i & 31) * 2;
            const int n = n0 + nl, h = n >> 6, dh = n & 63;
            const int bh = bb * NH + h;
            ((uint32_t*)g_vt16)[((size_t)(bh * 32 + kt)) * 2048
                                + bfragv_off(dh, s2)] =
                *(const uint32_t*)&vt[nl * 72 + s2];
        }
    }
}

// ---------------------------------------------------------------------------
// Output projection (128 threads): g_aoh @ g_wo16 -> out = acc/32 + bo
// ---------------------------------------------------------------------------
__global__ __launch_bounds__(128, 4) void out_gemm(
    const float* __restrict__ bo, float* __restrict__ out)
{
    extern __shared__ char sm[];
    const int m0 = blockIdx.y * 64, n0 = blockIdx.x * 128;
    float acc[4][4][4];
    gemm_f16_core(g_aoh, g_wo16, sm, blockIdx.y, blockIdx.x, acc);

    const int tid = threadIdx.x, wn = tid >> 5, lane = tid & 31;
    const int g = lane >> 2, tg = lane & 3;
    const float sc = 0.03125f;

    #pragma unroll
    for (int mt = 0; mt < 4; mt++) {
        #pragma unroll
        for (int nt = 0; nt < 4; nt++) {
            const int n = n0 + wn * 32 + nt * 8 + 2 * tg;
            float b0 = bo[n], b1 = bo[n + 1];
            #pragma unroll
            for (int half = 0; half < 2; half++) {
                const int r = m0 + mt * 16 + g + half * 8;
                float2 v = make_float2(acc[mt][nt][2 * half] * sc + b0,
                                       acc[mt][nt][2 * half + 1] * sc + b1);
                *(float2*)&out[(size_t)r * ND + n] = v;
            }
        }
    }
}

// ---------------------------------------------------------------------------
// Flash attention, 128 threads / 64 q-rows / 4 CTAs per SM.
// K and V^T in vectorized B-frag tiles: two fragments per LDS.128.
// Stage = K tile 8KB + V tile 8KB; 3-stage cp.async, 1 barrier per k-tile.
// ---------------------------------------------------------------------------
#define ATT_STAGE 16384
#define ATT_SMEM  (3 * ATT_STAGE)   // 49152

__global__ __launch_bounds__(128, 4) void attn_kernel(const int* __restrict__ mask)
{
    extern __shared__ char att_sm[];
    __shared__ float mb[3][64];

    const int bh = blockIdx.y;
    const int b  = bh >> 4;
    const int h  = bh & 15;
    const int q0 = blockIdx.x * 64;
    const float* Qp = g_q + (size_t)bh * NS * NDH;
    const unsigned short* KT = g_kt16 + (size_t)bh * 32 * 4096;
    const unsigned short* VT = g_vt16 + (size_t)bh * 32 * 4096;
    const int* mrow = mask + b * NS;

    const int tid = threadIdx.x, wid = tid >> 5, lane = tid & 31;
    const int g = lane >> 2, tg = lane & 3;
    const uint32_t sb = smem_u32(att_sm);

    auto issue = [&](int kb, int bf) {
        const uint32_t st = sb + bf * ATT_STAGE;
        const unsigned short* kp = KT + (size_t)kb * 4096;
        const unsigned short* vp = VT + (size_t)kb * 4096;
        #pragma unroll
        for (int i = 0; i < 4; i++) {
            const int f = tid + i * 128;
            CP16(st +        f * 16, kp + f * 8);
            CP16(st + 8192 + f * 16, vp + f * 8);
        }
        CP_COMMIT();
    };

    const float qs = 0.125f * LOG2E;
    uint32_t qh[4][4];
    {
        const float* q0p = Qp + (size_t)(q0 + wid * 16 + g) * NDH;
        const float* q1p = q0p + 8 * NDH;
        #pragma unroll
        for (int kk = 0; kk < 4; kk++) {
            float2 x;
            x = *(const float2*)(q0p + kk * 16 + 2 * tg);
            qh[kk][0] = pack_h2(qs * x.x, qs * x.y);
            x = *(const float2*)(q1p + kk * 16 + 2 * tg);
            qh[kk][1] = pack_h2(qs * x.x, qs * x.y);
            x = *(const float2*)(q0p + kk * 16 + 2 * tg + 8);
            qh[kk][2] = pack_h2(qs * x.x, qs * x.y);
            x = *(const float2*)(q1p + kk * 16 + 2 * tg + 8);
            qh[kk][3] = pack_h2(qs * x.x, qs * x.y);
        }
    }

    float o[8][4];
    #pragma unroll
    for (int nt = 0; nt < 8; nt++)
        #pragma unroll
        for (int i = 0; i < 4; i++) o[nt][i] = 0.f;
    float mrun[2] = {-1e30f, -1e30f}, lrun[2] = {0.f, 0.f};

    issue(0, 0);
    issue(1, 1);
    if (tid < 64) {
        mb[0][tid] = mrow[tid]      ? 0.f : -1e30f;
        mb[1][tid] = mrow[64 + tid] ? 0.f : -1e30f;
    }

    for (int kb = 0; kb < NS / 64; kb++) {
        const int bf = kb % 3;
        if (kb == NS / 64 - 1) CP_WAIT0(); else CP_WAIT1();
        __syncthreads();
        if (kb + 2 < NS / 64) {
            issue(kb + 2, (kb + 2) % 3);
            if (tid < 64)
                mb[(kb + 2) % 3][tid] = mrow[(kb + 2) * 64 + tid] ? 0.f : -1e30f;
        }

        const uint4* K4 = (const uint4*)(att_sm + bf * ATT_STAGE);
        const uint4* V4 = (const uint4*)(att_sm + bf * ATT_STAGE + 8192);

        // ---- S (log2 domain) = Q K^T : 1 LDS.128 per 2 fragments ----
        float sc[8][4];
        #pragma unroll
        for (int nt = 0; nt < 8; nt++)
            #pragma unroll
            for (int i = 0; i < 4; i++) sc[nt][i] = 0.f;

        #pragma unroll
        for (int kk = 0; kk < 4; kk++) {
            #pragma unroll
            for (int j = 0; j < 4; j++) {
                uint4 t = K4[(kk * 4 + j) * 32 + lane];
                uint32_t b2a[2] = { t.x, t.y };
                mma_fp16(sc[2 * j],     qh[kk], b2a);
                uint32_t b2b[2] = { t.z, t.w };
                mma_fp16(sc[2 * j + 1], qh[kk], b2b);
            }
        }

        // ---- mask bias ----
        #pragma unroll
        for (int nt = 0; nt < 8; nt++) {
            float2 mv = *(const float2*)&mb[bf][nt * 8 + 2 * tg];
            sc[nt][0] += mv.x; sc[nt][1] += mv.y;
            sc[nt][2] += mv.x; sc[nt][3] += mv.y;
        }

        // ---- online softmax, log2 domain (rows g, g+8; quad shfl) ----
        #pragma unroll
        for (int r = 0; r < 2; r++) {
            float mx = -1e30f;
            #pragma unroll
            for (int nt = 0; nt < 8; nt++)
                mx = fmaxf(mx, fmaxf(sc[nt][2 * r], sc[nt][2 * r + 1]));
            mx = fmaxf(mx, __shfl_xor_sync(0xffffffffu, mx, 1));
            mx = fmaxf(mx, __shfl_xor_sync(0xffffffffu, mx, 2));
            const float mn = fmaxf(mrun[r], mx);
            float sum = 0.f;
            #pragma unroll
            for (int nt = 0; nt < 8; nt++) {
                float p0 = ex2f(sc[nt][2 * r]     - mn);
                float p1 = ex2f(sc[nt][2 * r + 1] - mn);
                sc[nt][2 * r] = p0; sc[nt][2 * r + 1] = p1;
                sum += p0 + p1;
            }
            sum += __shfl_xor_sync(0xffffffffu, sum, 1);
            sum += __shfl_xor_sync(0xffffffffu, sum, 2);
            const float al = ex2f(mrun[r] - mn);
            lrun[r] = lrun[r] * al + sum;
            mrun[r] = mn;
            #pragma unroll
            for (int nt = 0; nt < 8; nt++) {
                o[nt][2 * r]     *= al;
                o[nt][2 * r + 1] *= al;
            }
        }

        // ---- O += P V : 1 LDS.128 per 2 fragments ----
        #pragma unroll
        for (int kk = 0; kk < 4; kk++) {
            uint32_t ph[4];
            ph[0] = pack_h2(sc[2 * kk][0],     sc[2 * kk][1]);
            ph[1] = pack_h2(sc[2 * kk][2],     sc[2 * kk][3]);
            ph[2] = pack_h2(sc[2 * kk + 1][0], sc[2 * kk + 1][1]);
            ph[3] = pack_h2(sc[2 * kk + 1][2], sc[2 * kk + 1][3]);
            #pragma unroll
            for (int j = 0; j < 4; j++) {
                uint4 t = V4[(kk * 4 + j) * 32 + lane];
                uint32_t v2a[2] = { t.x, t.y };
                mma_fp16(o[2 * j],     ph, v2a);
                uint32_t v2b[2] = { t.z, t.w };
                mma_fp16(o[2 * j + 1], ph, v2b);
            }
        }
    }

    // ---- normalize + pack single fp16 + write 64-row A-frag layout ----
    const float inv0 = 1.0f / lrun[0];
    const float inv1 = 1.0f / lrun[1];
    const int m_lo = b * NS + q0 + wid * 16 + g;
    const int m_hi = m_lo + 8;
    uint32_t* aoh32 = (uint32_t*)g_aoh;
    #pragma unroll
    for (int nt = 0; nt < 8; nt++) {
        const int col = h * 64 + nt * 8 + 2 * tg;
        aoh32[af16_off(m_lo, col)] = pack_h2(o[nt][0] * inv0, o[nt][1] * inv0);
        aoh32[af16_off(m_hi, col)] = pack_h2(o[nt][2] * inv1, o[nt][3] * inv1);
    }
}

// ---------------------------------------------------------------------------
extern "C" void kernel_launch(void* const* d_in, const int* in_sizes, int n_in,
                              void* d_out, int out_size)
{
    const float* hs  = (const float*)d_in[0];
    const int*   msk = (const int*)  d_in[1];
    const float* Wq  = (const float*)d_in[2];
    const float* bq  = (const float*)d_in[3];
    const float* Wk  = (const float*)d_in[4];
    const float* bk  = (const float*)d_in[5];
    const float* Wv  = (const float*)d_in[6];
    const float* bv  = (const float*)d_in[7];
    const float* emo = (const float*)d_in[8];
    const float* Wo  = (const float*)d_in[9];
    const float* bo  = (const float*)d_in[10];
    float* out = (float*)d_out;

    cudaFuncSetAttribute(qkv_gemm, cudaFuncAttributeMaxDynamicSharedMemorySize, GEMM_SMEM);
    cudaFuncSetAttribute(out_gemm, cudaFuncAttributeMaxDynamicSharedMemorySize, GEMM_SMEM);
    cudaFuncSetAttribute(attn_kernel, cudaFuncAttributeMaxDynamicSharedMemorySize, ATT_SMEM);

    dim3 gr(128, 5);
    round_prep<<<gr, 256>>>(hs, Wq, Wk, Wv, Wo);

    dim3 gqkv(ND / 128, MT / 64, 3);
    qkv_gemm<<<gqkv, 128, GEMM_SMEM>>>(bq, bk, bv, emo);

    dim3 gatt(NS / 64, NB * NH);
    attn_kernel<<<gatt, 128, ATT_SMEM>>>(msk);

    dim3 gout(ND / 128, MT / 64);
    out_gemm<<<gout, 128, GEMM_SMEM>>>(bo, out);
}